// round 15
// baseline (speedup 1.0000x reference)
#include <cuda_runtime.h>
#include <cuda_bf16.h>
#include <cstdint>

// Problem constants
#define Bsz 4
#define T 1024
#define C 1024
#define H 16
#define HD 64
#define C3 3072

// Scratch (device globals: allocation-free rule)
__device__ __nv_bfloat16 g_ah[Bsz * T * C];    // A hi (x-split, then y-split)
__device__ __nv_bfloat16 g_al[Bsz * T * C];    // A lo
__device__ __nv_bfloat16 g_wth[C3 * C];        // W_attn^T hi
__device__ __nv_bfloat16 g_wtl[C3 * C];        // W_attn^T lo
__device__ __nv_bfloat16 g_wph[C * C];         // W_proj^T hi
__device__ __nv_bfloat16 g_wpl[C * C];         // W_proj^T lo
__device__ __nv_bfloat16 g_qvh[Bsz * T * C3];  // qkv hi bf16
__device__ __nv_bfloat16 g_qvl[Bsz * T * C3];  // qkv lo bf16

// ===========================================================================
// PTX helpers (sm_80+ features only: mma.sync / ldmatrix / cp.async)
// ===========================================================================
__device__ __forceinline__ uint32_t smem_u32(const void* p) {
    uint32_t a;
    asm("{ .reg .u64 t; cvta.to.shared.u64 t, %1; cvt.u32.u64 %0, t; }"
        : "=r"(a) : "l"(p));
    return a;
}
__device__ __forceinline__ void cp_async16(uint32_t dst, const void* src) {
    asm volatile("cp.async.cg.shared.global [%0], [%1], 16;"
                 :: "r"(dst), "l"(src) : "memory");
}
__device__ __forceinline__ void cp_commit() {
    asm volatile("cp.async.commit_group;" ::: "memory");
}
template <int N>
__device__ __forceinline__ void cp_wait() {
    asm volatile("cp.async.wait_group %0;" :: "n"(N) : "memory");
}
__device__ __forceinline__ void ldsm_x4(uint32_t& r0, uint32_t& r1,
                                        uint32_t& r2, uint32_t& r3, uint32_t a) {
    asm volatile("ldmatrix.sync.aligned.m8n8.x4.shared.b16 {%0,%1,%2,%3}, [%4];"
                 : "=r"(r0), "=r"(r1), "=r"(r2), "=r"(r3) : "r"(a));
}
__device__ __forceinline__ void ldsm_x4t(uint32_t& r0, uint32_t& r1,
                                         uint32_t& r2, uint32_t& r3, uint32_t a) {
    asm volatile("ldmatrix.sync.aligned.m8n8.x4.trans.shared.b16 {%0,%1,%2,%3}, [%4];"
                 : "=r"(r0), "=r"(r1), "=r"(r2), "=r"(r3) : "r"(a));
}
__device__ __forceinline__ void mma_bf16(float* c, uint32_t a0, uint32_t a1,
                                         uint32_t a2, uint32_t a3,
                                         uint32_t b0, uint32_t b1) {
    asm volatile(
        "mma.sync.aligned.m16n8k16.row.col.f32.bf16.bf16.f32 "
        "{%0,%1,%2,%3}, {%4,%5,%6,%7}, {%8,%9}, {%0,%1,%2,%3};"
        : "+f"(c[0]), "+f"(c[1]), "+f"(c[2]), "+f"(c[3])
        : "r"(a0), "r"(a1), "r"(a2), "r"(a3), "r"(b0), "r"(b1));
}
__device__ __forceinline__ void split2(float a, float b,
                                       uint32_t& hout, uint32_t& lout) {
    __nv_bfloat162 h = __floats2bfloat162_rn(a, b);
    float2 f = __bfloat1622float2(h);
    __nv_bfloat162 l = __floats2bfloat162_rn(a - f.x, b - f.y);
    hout = *(uint32_t*)&h;
    lout = *(uint32_t*)&l;
}

// ===========================================================================
// fp32 -> bf16 hi/lo split (vectorized by 4)
// ===========================================================================
__global__ __launch_bounds__(256) void split_kernel(
    const float* __restrict__ src, __nv_bfloat16* __restrict__ hi,
    __nv_bfloat16* __restrict__ lo, int n4)
{
    int i = blockIdx.x * 256 + threadIdx.x;
    if (i >= n4) return;
    float4 v = ((const float4*)src)[i];
    uint32_t h0, l0, h1, l1;
    split2(v.x, v.y, h0, l0);
    split2(v.z, v.w, h1, l1);
    ((uint32_t*)hi)[2 * i + 0] = h0;
    ((uint32_t*)hi)[2 * i + 1] = h1;
    ((uint32_t*)lo)[2 * i + 0] = l0;
    ((uint32_t*)lo)[2 * i + 1] = l1;
}

// ===========================================================================
// Transpose + split: W (K x N) -> Wt_hi/lo (N x K) bf16
// ===========================================================================
__global__ __launch_bounds__(256) void tsplit_kernel(
    const float* __restrict__ W, __nv_bfloat16* __restrict__ Th,
    __nv_bfloat16* __restrict__ Tl, int K, int N)
{
    __shared__ float t[32][33];
    int n0 = blockIdx.x * 32, k0 = blockIdx.y * 32;
    int tx = threadIdx.x, ty = threadIdx.y;
#pragma unroll
    for (int i = 0; i < 32; i += 8)
        t[ty + i][tx] = W[(size_t)(k0 + ty + i) * N + n0 + tx];
    __syncthreads();
#pragma unroll
    for (int i = 0; i < 32; i += 8) {
        float v = t[tx][ty + i];
        __nv_bfloat16 h = __float2bfloat16(v);
        __nv_bfloat16 l = __float2bfloat16(v - __bfloat162float(h));
        size_t o = (size_t)(n0 + ty + i) * K + k0 + tx;
        Th[o] = h; Tl[o] = l;
    }
}

// ===========================================================================
// mma.sync bf16x3 GEMM. MMA order: product-type outermost within each B-half
// so consecutive MMAs hit 8 distinct accumulators (hides HMMA acc-RAW).
// ===========================================================================
#define GK 32
#define ROWB 80                        // 64B data + 16B pad per row
#define MATB (128 * ROWB)              // 10240
#define STAGEB (4 * MATB)              // 40960
#define GEMM_SMEM_BYTES (2 * STAGEB)   // 81920

__global__ __launch_bounds__(256, 2) void gemm_mma_kernel(
    const __nv_bfloat16* __restrict__ Ah, const __nv_bfloat16* __restrict__ Al,
    const __nv_bfloat16* __restrict__ Bh, const __nv_bfloat16* __restrict__ Bl,
    const float* __restrict__ bias, float* __restrict__ Cf,
    __nv_bfloat16* __restrict__ Oh, __nv_bfloat16* __restrict__ Ol,
    int M, int N, int K)
{
    extern __shared__ char smem[];
    const uint32_t sb = smem_u32(smem);

    const int tid  = threadIdx.x;
    const int wid  = tid >> 5;
    const int lane = tid & 31;
    const int wm   = wid >> 1;
    const int wn   = wid & 1;
    const int brow = blockIdx.y * 128;
    const int bcol = blockIdx.x * 128;

    const __nv_bfloat16* gbase[4] = {
        Ah + (size_t)brow * K, Al + (size_t)brow * K,
        Bh + (size_t)bcol * K, Bl + (size_t)bcol * K };

    auto issue_stage = [&](int c, int stage) {
        const int kbase = c * GK;
        const uint32_t sst = sb + stage * STAGEB;
#pragma unroll
        for (int m = 0; m < 4; m++) {
            const __nv_bfloat16* gb = gbase[m] + kbase;
            const uint32_t ms = sst + m * MATB;
#pragma unroll
            for (int it = 0; it < 2; it++) {
                int idx = it * 256 + tid;
                int row = idx >> 2, ch = idx & 3;
                cp_async16(ms + row * ROWB + ch * 16,
                           gb + (size_t)row * K + ch * 8);
            }
        }
        cp_commit();
    };

    float acc[2][8][4];
#pragma unroll
    for (int i = 0; i < 2; i++)
#pragma unroll
        for (int j = 0; j < 8; j++)
#pragma unroll
            for (int r = 0; r < 4; r++) acc[i][j][r] = 0.0f;

    const int nchunks = K / GK;   // 32
    issue_stage(0, 0);

    const int aRow = (wm * 32) + (lane & 15);
    const int aK   = (lane >> 4) * 16;
    const int bRow = (wn * 64) + (lane & 7) + ((lane >> 4) << 3);
    const int bK   = ((lane >> 3) & 1) * 16;

    for (int c = 0; c < nchunks; c++) {
        if (c + 1 < nchunks) {
            issue_stage(c + 1, (c + 1) & 1);
            cp_wait<1>();
        } else {
            cp_wait<0>();
        }
        __syncthreads();

        const uint32_t sst = sb + (c & 1) * STAGEB;
        const uint32_t ahBase = sst + 0 * MATB;
        const uint32_t alBase = sst + 1 * MATB;
        const uint32_t bhBase = sst + 2 * MATB;
        const uint32_t blBase = sst + 3 * MATB;

#pragma unroll
        for (int ks = 0; ks < 2; ks++) {
            const int ko = ks * 32;
            uint32_t ahf[2][4], alf[2][4];
#pragma unroll
            for (int mt = 0; mt < 2; mt++) {
                uint32_t off = (uint32_t)((aRow + mt * 16) * ROWB + ko + aK);
                ldsm_x4(ahf[mt][0], ahf[mt][1], ahf[mt][2], ahf[mt][3], ahBase + off);
                ldsm_x4(alf[mt][0], alf[mt][1], alf[mt][2], alf[mt][3], alBase + off);
            }
#pragma unroll
            for (int half = 0; half < 2; half++) {
                uint32_t bhf[4][2], blf[4][2];
#pragma unroll
                for (int jp = 0; jp < 2; jp++) {
                    uint32_t off = (uint32_t)(((half * 2 + jp) * 16 + bRow) * ROWB + ko + bK);
                    ldsm_x4(bhf[2*jp][0], bhf[2*jp][1], bhf[2*jp+1][0], bhf[2*jp+1][1],
                            bhBase + off);
                    ldsm_x4(blf[2*jp][0], blf[2*jp][1], blf[2*jp+1][0], blf[2*jp+1][1],
                            blBase + off);
                }
                // product-type outermost: consecutive MMAs -> 8 distinct accs
#pragma unroll
                for (int mt = 0; mt < 2; mt++)
#pragma unroll
                    for (int n4 = 0; n4 < 4; n4++)
                        mma_bf16(acc[mt][half * 4 + n4],
                                 ahf[mt][0], ahf[mt][1], ahf[mt][2], ahf[mt][3],
                                 bhf[n4][0], bhf[n4][1]);
#pragma unroll
                for (int mt = 0; mt < 2; mt++)
#pragma unroll
                    for (int n4 = 0; n4 < 4; n4++)
                        mma_bf16(acc[mt][half * 4 + n4],
                                 ahf[mt][0], ahf[mt][1], ahf[mt][2], ahf[mt][3],
                                 blf[n4][0], blf[n4][1]);
#pragma unroll
                for (int mt = 0; mt < 2; mt++)
#pragma unroll
                    for (int n4 = 0; n4 < 4; n4++)
                        mma_bf16(acc[mt][half * 4 + n4],
                                 alf[mt][0], alf[mt][1], alf[mt][2], alf[mt][3],
                                 bhf[n4][0], bhf[n4][1]);
            }
        }
        __syncthreads();
    }

    const int rbase = brow + wm * 32 + (lane >> 2);
    const int cbase = bcol + wn * 64 + (lane & 3) * 2;
#pragma unroll
    for (int mt = 0; mt < 2; mt++) {
#pragma unroll
        for (int nt = 0; nt < 8; nt++) {
            int row = rbase + mt * 16;
            int col = cbase + nt * 8;
            float2 bb = *(const float2*)(bias + col);
            float v0 = acc[mt][nt][0] + bb.x;
            float v1 = acc[mt][nt][1] + bb.y;
            float v2 = acc[mt][nt][2] + bb.x;
            float v3 = acc[mt][nt][3] + bb.y;
            if (Cf) {
                *(float2*)(Cf + (size_t)row * N + col) = make_float2(v0, v1);
                *(float2*)(Cf + (size_t)(row + 8) * N + col) = make_float2(v2, v3);
            }
            if (Oh) {
                uint32_t h0, l0, h1, l1;
                split2(v0, v1, h0, l0);
                split2(v2, v3, h1, l1);
                *(uint32_t*)(Oh + (size_t)row * N + col) = h0;
                *(uint32_t*)(Ol + (size_t)row * N + col) = l0;
                *(uint32_t*)(Oh + (size_t)(row + 8) * N + col) = h1;
                *(uint32_t*)(Ol + (size_t)(row + 8) * N + col) = l1;
            }
        }
    }
}

// ===========================================================================
// Tensor-core flash attention (64-query CTAs), MMA order interleaved so
// consecutive MMAs target distinct accumulators.
// ===========================================================================
#define FROWB 144
#define FMATB (64 * FROWB)
#define FPADB 4096
#define FSTAGEB (4 * FMATB + FPADB)
#define FQ_BYTES (2 * FMATB)
#define FLASH_SMEM (FQ_BYTES + 2 * FSTAGEB)

__global__ __launch_bounds__(128) void flash_mma_kernel(
    const __nv_bfloat16* __restrict__ qvh, const __nv_bfloat16* __restrict__ qvl,
    const unsigned char* __restrict__ pad,
    __nv_bfloat16* __restrict__ yh, __nv_bfloat16* __restrict__ yl)
{
    extern __shared__ char fsm[];
    const uint32_t sb = smem_u32(fsm);
    const int tid = threadIdx.x, lane = tid & 31, w = tid >> 5;
    const int qt = blockIdx.x;
    const int bh = blockIdx.y;
    const int b = bh >> 4, h = bh & 15;
    const int q0 = qt * 64;

    const uint32_t sQh = sb;
    const uint32_t sQl = sQh + FMATB;
    const uint32_t sStage = sQl + FMATB;

    {
        const size_t rbase = (size_t)(b * T + q0) * C3 + h * HD;
#pragma unroll
        for (int it = 0; it < 4; it++) {
            int idx = it * 128 + tid;
            int row = idx >> 3, ch = idx & 7;
            float4 vh = *(const float4*)(qvh + rbase + (size_t)row * C3 + ch * 8);
            float4 vl = *(const float4*)(qvl + rbase + (size_t)row * C3 + ch * 8);
            *(float4*)(fsm + (sQh - sb) + row * FROWB + ch * 16) = vh;
            *(float4*)(fsm + (sQl - sb) + row * FROWB + ch * 16) = vl;
        }
    }

    auto load_stage = [&](int kt, int stg) {
        const uint32_t ss = sStage + stg * FSTAGEB;
        const int kr0 = kt * 64;
        const __nv_bfloat16* srcs[4] = {
            qvh + C + h * HD, qvl + C + h * HD,
            qvh + 2 * C + h * HD, qvl + 2 * C + h * HD };
#pragma unroll
        for (int m = 0; m < 4; m++) {
            const __nv_bfloat16* s = srcs[m];
            const uint32_t ms = ss + m * FMATB;
#pragma unroll
            for (int it = 0; it < 4; it++) {
                int idx = it * 128 + tid;
                int row = idx >> 3, ch = idx & 7;
                cp_async16(ms + row * FROWB + ch * 16,
                           s + (size_t)(b * T + kr0 + row) * C3 + ch * 8);
            }
        }
        const uint32_t ps = ss + 4 * FMATB;
#pragma unroll
        for (int it = 0; it < 2; it++) {
            int idx = it * 128 + tid;
            int row = idx >> 2, ch = idx & 3;
            cp_async16(ps + row * 64 + ch * 16,
                       pad + (size_t)(b * T + q0 + row) * T + kr0 + ch * 16);
        }
        cp_commit();
    };

    const int nkt = qt + 1;
    load_stage(0, 0);
    __syncthreads();

    uint32_t qhF[4][4], qlF[4][4];
    {
        const uint32_t off0 = (uint32_t)((w * 16 + (lane & 15)) * FROWB + (lane >> 4) * 16);
#pragma unroll
        for (int ks = 0; ks < 4; ks++) {
            ldsm_x4(qhF[ks][0], qhF[ks][1], qhF[ks][2], qhF[ks][3], sQh + off0 + ks * 32);
            ldsm_x4(qlF[ks][0], qlF[ks][1], qlF[ks][2], qlF[ks][3], sQl + off0 + ks * 32);
        }
    }

    float o[8][4];
#pragma unroll
    for (int nt = 0; nt < 8; nt++)
#pragma unroll
        for (int r = 0; r < 4; r++) o[nt][r] = 0.0f;
    float m0 = -1e30f, m1 = -1e30f, l0 = 0.0f, l1 = 0.0f;

    const int r0l = w * 16 + (lane >> 2);
    const int gq0 = q0 + r0l, gq1 = gq0 + 8;

    for (int kt = 0; kt < nkt; kt++) {
        if (kt + 1 < nkt) {
            load_stage(kt + 1, (kt + 1) & 1);
            cp_wait<1>();
        } else {
            cp_wait<0>();
        }
        __syncthreads();

        const uint32_t ss = sStage + (kt & 1) * FSTAGEB;
        const uint32_t sKh = ss, sKl = ss + FMATB;
        const uint32_t sVh = ss + 2 * FMATB, sVl = ss + 3 * FMATB;
        const char* pdp = fsm + (ss - sb) + 4 * FMATB;

        // ---- S = QK^T (bf16x3); product-type outermost per ks ----
        float s[8][4];
#pragma unroll
        for (int nt = 0; nt < 8; nt++)
#pragma unroll
            for (int r = 0; r < 4; r++) s[nt][r] = 0.0f;

        const int bRow = (lane & 7) + ((lane >> 4) << 3);
        const int bK   = ((lane >> 3) & 1) * 16;
#pragma unroll
        for (int ks = 0; ks < 4; ks++) {
            uint32_t kh[8][2], kl[8][2];
#pragma unroll
            for (int jp = 0; jp < 4; jp++) {
                uint32_t off = (uint32_t)((jp * 16 + bRow) * FROWB + bK + ks * 32);
                ldsm_x4(kh[2*jp][0], kh[2*jp][1], kh[2*jp+1][0], kh[2*jp+1][1], sKh + off);
                ldsm_x4(kl[2*jp][0], kl[2*jp][1], kl[2*jp+1][0], kl[2*jp+1][1], sKl + off);
            }
#pragma unroll
            for (int nt = 0; nt < 8; nt++)
                mma_bf16(s[nt], qhF[ks][0], qhF[ks][1], qhF[ks][2], qhF[ks][3],
                         kh[nt][0], kh[nt][1]);
#pragma unroll
            for (int nt = 0; nt < 8; nt++)
                mma_bf16(s[nt], qhF[ks][0], qhF[ks][1], qhF[ks][2], qhF[ks][3],
                         kl[nt][0], kl[nt][1]);
#pragma unroll
            for (int nt = 0; nt < 8; nt++)
                mma_bf16(s[nt], qlF[ks][0], qlF[ks][1], qlF[ks][2], qlF[ks][3],
                         kh[nt][0], kh[nt][1]);
        }

        const bool diag = (kt == qt);
#pragma unroll
        for (int nt = 0; nt < 8; nt++) {
            int cl = nt * 8 + (lane & 3) * 2;
            int gk = kt * 64 + cl;
            unsigned short pd0 = *(const unsigned short*)(pdp + r0l * 64 + cl);
            unsigned short pd1 = *(const unsigned short*)(pdp + (r0l + 8) * 64 + cl);
            s[nt][0] *= 0.125f; s[nt][1] *= 0.125f;
            s[nt][2] *= 0.125f; s[nt][3] *= 0.125f;
            if ((diag && gk > gq0)     || (pd0 & 0x00FF)) s[nt][0] = -1e30f;
            if ((diag && gk + 1 > gq0) || (pd0 & 0xFF00)) s[nt][1] = -1e30f;
            if ((diag && gk > gq1)     || (pd1 & 0x00FF)) s[nt][2] = -1e30f;
            if ((diag && gk + 1 > gq1) || (pd1 & 0xFF00)) s[nt][3] = -1e30f;
        }

        float mx0 = -1e30f, mx1 = -1e30f;
#pragma unroll
        for (int nt = 0; nt < 8; nt++) {
            mx0 = fmaxf(mx0, fmaxf(s[nt][0], s[nt][1]));
            mx1 = fmaxf(mx1, fmaxf(s[nt][2], s[nt][3]));
        }
        mx0 = fmaxf(mx0, __shfl_xor_sync(0xFFFFFFFFu, mx0, 1));
        mx0 = fmaxf(mx0, __shfl_xor_sync(0xFFFFFFFFu, mx0, 2));
        mx1 = fmaxf(mx1, __shfl_xor_sync(0xFFFFFFFFu, mx1, 1));
        mx1 = fmaxf(mx1, __shfl_xor_sync(0xFFFFFFFFu, mx1, 2));

        float mn0 = fmaxf(m0, mx0), mn1 = fmaxf(m1, mx1);
        float al0 = __expf(m0 - mn0), al1 = __expf(m1 - mn1);
        float live0 = (mn0 > -1e29f) ? 1.0f : 0.0f;
        float live1 = (mn1 > -1e29f) ? 1.0f : 0.0f;
        m0 = mn0; m1 = mn1;

        float ps0 = 0.f, ps1 = 0.f;
#pragma unroll
        for (int nt = 0; nt < 8; nt++) {
            s[nt][0] = live0 * __expf(s[nt][0] - mn0);
            s[nt][1] = live0 * __expf(s[nt][1] - mn0);
            s[nt][2] = live1 * __expf(s[nt][2] - mn1);
            s[nt][3] = live1 * __expf(s[nt][3] - mn1);
            ps0 += s[nt][0] + s[nt][1];
            ps1 += s[nt][2] + s[nt][3];
        }
        l0 = l0 * al0 + ps0;   // per-lane partial; quad-reduced at epilogue
        l1 = l1 * al1 + ps1;
#pragma unroll
        for (int nt = 0; nt < 8; nt++) {
            o[nt][0] *= al0; o[nt][1] *= al0;
            o[nt][2] *= al1; o[nt][3] *= al1;
        }

        uint32_t pha[4][4], pla[4][4];
#pragma unroll
        for (int ks = 0; ks < 4; ks++) {
#pragma unroll
            for (int t2 = 0; t2 < 2; t2++) {
                int nt = 2 * ks + t2;
                split2(s[nt][0], s[nt][1], pha[ks][2 * t2 + 0], pla[ks][2 * t2 + 0]);
                split2(s[nt][2], s[nt][3], pha[ks][2 * t2 + 1], pla[ks][2 * t2 + 1]);
            }
        }

        // ---- O += P V (bf16x3); product-type outermost per ks ----
#pragma unroll
        for (int ks = 0; ks < 4; ks++) {
            uint32_t vh[8][2], vl[8][2];
#pragma unroll
            for (int nb = 0; nb < 4; nb++) {
                uint32_t off = (uint32_t)((ks * 16 + (lane & 7) + ((lane >> 3) & 1) * 8) * FROWB
                                          + (nb * 16 + (lane >> 4) * 8) * 2);
                ldsm_x4t(vh[2*nb][0], vh[2*nb][1], vh[2*nb+1][0], vh[2*nb+1][1], sVh + off);
                ldsm_x4t(vl[2*nb][0], vl[2*nb][1], vl[2*nb+1][0], vl[2*nb+1][1], sVl + off);
            }
#pragma unroll
            for (int nt = 0; nt < 8; nt++)
                mma_bf16(o[nt], pha[ks][0], pha[ks][1], pha[ks][2], pha[ks][3],
                         vh[nt][0], vh[nt][1]);
#pragma unroll
            for (int nt = 0; nt < 8; nt++)
                mma_bf16(o[nt], pha[ks][0], pha[ks][1], pha[ks][2], pha[ks][3],
                         vl[nt][0], vl[nt][1]);
#pragma unroll
            for (int nt = 0; nt < 8; nt++)
                mma_bf16(o[nt], pla[ks][0], pla[ks][1], pla[ks][2], pla[ks][3],
                         vh[nt][0], vh[nt][1]);
        }
        __syncthreads();
    }

    l0 += __shfl_xor_sync(0xFFFFFFFFu, l0, 1);
    l0 += __shfl_xor_sync(0xFFFFFFFFu, l0, 2);
    l1 += __shfl_xor_sync(0xFFFFFFFFu, l1, 1);
    l1 += __shfl_xor_sync(0xFFFFFFFFu, l1, 2);

    float inv0 = (l0 > 0.f) ? (1.0f / l0) : 0.0f;
    float inv1 = (l1 > 0.f) ? (1.0f / l1) : 0.0f;
    const size_t row0 = (size_t)(b * T + gq0);
    const size_t row1 = (size_t)(b * T + gq1);
    const int cb = h * HD + (lane & 3) * 2;
#pragma unroll
    for (int nt = 0; nt < 8; nt++) {
        uint32_t h0, l0b, h1, l1b;
        split2(o[nt][0] * inv0, o[nt][1] * inv0, h0, l0b);
        split2(o[nt][2] * inv1, o[nt][3] * inv1, h1, l1b);
        *(uint32_t*)(yh + row0 * C + cb + nt * 8) = h0;
        *(uint32_t*)(yl + row0 * C + cb + nt * 8) = l0b;
        *(uint32_t*)(yh + row1 * C + cb + nt * 8) = h1;
        *(uint32_t*)(yl + row1 * C + cb + nt * 8) = l1b;
    }
}

// ---------------------------------------------------------------------------
// Head-0 raw logits from bf16 hi/lo qkv (exact R11 passing version)
// ---------------------------------------------------------------------------
__global__ __launch_bounds__(128) void att_scores_kernel(
    const __nv_bfloat16* __restrict__ qvh, const __nv_bfloat16* __restrict__ qvl,
    float* __restrict__ att)
{
    const int b  = blockIdx.z;
    const int qt = blockIdx.x;
    const int kt = blockIdx.y;
    const int kbase = kt * 64;
    if (kbase > qt * 128 + 127) return;

    __shared__ float Ks[64 * 64];
    const int tid = threadIdx.x;
#pragma unroll
    for (int i = 0; i < 4; i++) {
        int slot = tid + i * 128;
        int r = slot >> 3;
        int d8 = (slot & 7) * 8;
        const size_t go = (size_t)(b * T + kbase + r) * C3 + C + d8;
        uint4 uh = *(const uint4*)(qvh + go);
        uint4 ul = *(const uint4*)(qvl + go);
        const __nv_bfloat162* ph = (const __nv_bfloat162*)&uh;
        const __nv_bfloat162* pl = (const __nv_bfloat162*)&ul;
        float* dst = Ks + r * 64 + d8;
#pragma unroll
        for (int j = 0; j < 4; j++) {
            float2 fh = __bfloat1622float2(ph[j]);
            float2 fl = __bfloat1622float2(pl[j]);
            dst[2 * j + 0] = fh.x + fl.x;
            dst[2 * j + 1] = fh.y + fl.y;
        }
    }
    const int qi = qt * 128 + tid;
    const size_t qo = (size_t)(b * T + qi) * C3;
    float q[64];
#pragma unroll
    for (int i = 0; i < 8; i++) {
        uint4 uh = *(const uint4*)(qvh + qo + i * 8);
        uint4 ul = *(const uint4*)(qvl + qo + i * 8);
        const __nv_bfloat162* ph = (const __nv_bfloat162*)&uh;
        const __nv_bfloat162* pl = (const __nv_bfloat162*)&ul;
#pragma unroll
        for (int j = 0; j < 4; j++) {
            float2 fh = __bfloat1622float2(ph[j]);
            float2 fl = __bfloat1622float2(pl[j]);
            q[i * 8 + 2 * j + 0] = fh.x + fl.x;
            q[i * 8 + 2 * j + 1] = fh.y + fl.y;
        }
    }
    __syncthreads();

    float* op = att + (size_t)(b * T + qi) * T + kbase;
#pragma unroll
    for (int j0 = 0; j0 < 64; j0 += 4) {
        float sv[4];
#pragma unroll
        for (int jj = 0; jj < 4; jj++) {
            int j = j0 + jj;
            float a0 = 0.f, a1 = 0.f, a2 = 0.f, a3 = 0.f;
#pragma unroll
            for (int d4 = 0; d4 < 16; d4 += 4) {
                float4 k0 = *(const float4*)(Ks + j * 64 + (d4 + 0) * 4);
                float4 k1 = *(const float4*)(Ks + j * 64 + (d4 + 1) * 4);
                float4 k2 = *(const float4*)(Ks + j * 64 + (d4 + 2) * 4);
                float4 k3 = *(const float4*)(Ks + j * 64 + (d4 + 3) * 4);
                a0 += q[(d4+0)*4+0]*k0.x + q[(d4+0)*4+1]*k0.y + q[(d4+0)*4+2]*k0.z + q[(d4+0)*4+3]*k0.w;
                a1 += q[(d4+1)*4+0]*k1.x + q[(d4+1)*4+1]*k1.y + q[(d4+1)*4+2]*k1.z + q[(d4+1)*4+3]*k1.w;
                a2 += q[(d4+2)*4+0]*k2.x + q[(d4+2)*4+1]*k2.y + q[(d4+2)*4+2]*k2.z + q[(d4+2)*4+3]*k2.w;
                a3 += q[(d4+3)*4+0]*k3.x + q[(d4+3)*4+1]*k3.y + q[(d4+3)*4+2]*k3.z + q[(d4+3)*4+3]*k3.w;
            }
            sv[jj] = (a0 + a1 + a2 + a3) * 0.125f;
        }
        float4 r = make_float4(sv[0], sv[1], sv[2], sv[3]);
        *(float4*)(op + j0) = r;
    }
}

// ---------------------------------------------------------------------------
// In-place masked row softmax over att (B*T rows, T cols). Masked -> exactly 0.
// ---------------------------------------------------------------------------
__global__ __launch_bounds__(256) void att_softmax_kernel(
    float* __restrict__ att, const unsigned char* __restrict__ pad)
{
    const int row = blockIdx.x;
    const int qi = row & (T - 1);
    float* rp = att + (size_t)row * T;
    const unsigned char* pm = pad + (size_t)row * T;
    const int t = threadIdx.x;

    float x[4];
    float lmax = -1e30f;
#pragma unroll
    for (int i = 0; i < 4; i++) {
        int kj = t + i * 256;
        float v = rp[kj];
        bool m = (kj > qi) || pm[kj];
        x[i] = m ? -1e30f : v;
        lmax = fmaxf(lmax, x[i]);
    }
#pragma unroll
    for (int off = 16; off; off >>= 1)
        lmax = fmaxf(lmax, __shfl_xor_sync(0xFFFFFFFFu, lmax, off));

    __shared__ float sred[8];
    __shared__ float sM, sS;
    const int wid = t >> 5, lane = t & 31;
    if (lane == 0) sred[wid] = lmax;
    __syncthreads();
    if (t == 0) {
        float m = sred[0];
#pragma unroll
        for (int i = 1; i < 8; i++) m = fmaxf(m, sred[i]);
        sM = m;
    }
    __syncthreads();
    const float M = sM;

    float ls = 0.f;
#pragma unroll
    for (int i = 0; i < 4; i++) {
        x[i] = __expf(x[i] - M);
        ls += x[i];
    }
#pragma unroll
    for (int off = 16; off; off >>= 1)
        ls += __shfl_xor_sync(0xFFFFFFFFu, ls, off);
    if (lane == 0) sred[wid] = ls;
    __syncthreads();
    if (t == 0) {
        float s = 0.f;
#pragma unroll
        for (int i = 0; i < 8; i++) s += sred[i];
        sS = s;
    }
    __syncthreads();
    const float inv = (sS > 0.f) ? (1.0f / sS) : 0.0f;
#pragma unroll
    for (int i = 0; i < 4; i++) rp[t + i * 256] = x[i] * inv;
}

// ---------------------------------------------------------------------------
extern "C" void kernel_launch(void* const* d_in, const int* in_sizes, int n_in,
                              void* d_out, int out_size)
{
    const float* x      = (const float*)d_in[0];
    const float* W_attn = (const float*)d_in[1];
    const float* b_attn = (const float*)d_in[2];
    const float* W_proj = (const float*)d_in[3];
    const float* b_proj = (const float*)d_in[4];
    const unsigned char* pad = (const unsigned char*)d_in[5];

    float* y_out   = (float*)d_out;                      // (B,T,C)
    float* att_out = y_out + (size_t)Bsz * T * C;        // (B,1,T,T)

    __nv_bfloat16 *ah = nullptr, *al = nullptr, *wth = nullptr, *wtl = nullptr;
    __nv_bfloat16 *wph = nullptr, *wpl = nullptr;
    __nv_bfloat16 *qvh = nullptr, *qvl = nullptr;
    cudaGetSymbolAddress((void**)&ah, g_ah);
    cudaGetSymbolAddress((void**)&al, g_al);
    cudaGetSymbolAddress((void**)&wth, g_wth);
    cudaGetSymbolAddress((void**)&wtl, g_wtl);
    cudaGetSymbolAddress((void**)&wph, g_wph);
    cudaGetSymbolAddress((void**)&wpl, g_wpl);
    cudaGetSymbolAddress((void**)&qvh, g_qvh);
    cudaGetSymbolAddress((void**)&qvl, g_qvl);

    cudaFuncSetAttribute(gemm_mma_kernel,
                         cudaFuncAttributeMaxDynamicSharedMemorySize,
                         GEMM_SMEM_BYTES);
    cudaFuncSetAttribute(flash_mma_kernel,
                         cudaFuncAttributeMaxDynamicSharedMemorySize,
                         FLASH_SMEM);

    static cudaStream_t s_side = nullptr;
    static cudaEvent_t e_qkv = nullptr, e_att = nullptr, e_wp = nullptr,
                       e_fork = nullptr;
    if (!s_side) {
        cudaStreamCreateWithFlags(&s_side, cudaStreamNonBlocking);
        cudaEventCreateWithFlags(&e_qkv, cudaEventDisableTiming);
        cudaEventCreateWithFlags(&e_att, cudaEventDisableTiming);
        cudaEventCreateWithFlags(&e_wp, cudaEventDisableTiming);
        cudaEventCreateWithFlags(&e_fork, cudaEventDisableTiming);
    }

    const int Mrows = Bsz * T;  // 4096

    cudaEventRecord(e_fork, 0);
    cudaStreamWaitEvent(s_side, e_fork, 0);

    // side: transpose+split W_proj
    tsplit_kernel<<<dim3(C / 32, C / 32), dim3(32, 8), 0, s_side>>>(
        W_proj, wph, wpl, C, C);
    cudaEventRecord(e_wp, s_side);

    // main: split x; transpose+split W_attn
    split_kernel<<<(Mrows * C / 4 + 255) / 256, 256>>>(x, ah, al, Mrows * C / 4);
    tsplit_kernel<<<dim3(C3 / 32, C / 32), dim3(32, 8)>>>(W_attn, wth, wtl, C, C3);

    // main: qkv GEMM (bf16 hi/lo epilogue)
    gemm_mma_kernel<<<dim3(C3 / 128, Mrows / 128), 256, GEMM_SMEM_BYTES>>>(
        ah, al, wth, wtl, b_attn, nullptr, qvh, qvl, Mrows, C3, C);
    cudaEventRecord(e_qkv, 0);

    // side: head-0 att probabilities (concurrent with flash)
    cudaStreamWaitEvent(s_side, e_qkv, 0);
    att_scores_kernel<<<dim3(T / 128, T / 64, Bsz), 128, 0, s_side>>>(
        qvh, qvl, att_out);
    att_softmax_kernel<<<Bsz * T, 256, 0, s_side>>>(att_out, pad);
    cudaEventRecord(e_att, s_side);

    // main: flash attention -> y as bf16 hi/lo
    flash_mma_kernel<<<dim3(T / 64, Bsz * H), 128, FLASH_SMEM>>>(
        qvh, qvl, pad, ah, al);

    // main: proj GEMM
    cudaStreamWaitEvent(0, e_wp, 0);
    gemm_mma_kernel<<<dim3(C / 128, Mrows / 128), 256, GEMM_SMEM_BYTES>>>(
        ah, al, wph, wpl, b_proj, y_out, nullptr, nullptr, Mrows, C, C);

    cudaStreamWaitEvent(0, e_att, 0);
}

// round 16
// speedup vs baseline: 1.0044x; 1.0044x over previous
#include <cuda_runtime.h>
#include <cuda_bf16.h>
#include <cstdint>

// Problem constants
#define Bsz 4
#define T 1024
#define C 1024
#define H 16
#define HD 64
#define C3 3072

// Scratch (device globals: allocation-free rule)
__device__ __nv_bfloat16 g_ah[Bsz * T * C];    // A hi (x-split, then y-split)
__device__ __nv_bfloat16 g_al[Bsz * T * C];    // A lo
__device__ __nv_bfloat16 g_wth[C3 * C];        // W_attn^T hi
__device__ __nv_bfloat16 g_wtl[C3 * C];        // W_attn^T lo
__device__ __nv_bfloat16 g_wph[C * C];         // W_proj^T hi
__device__ __nv_bfloat16 g_wpl[C * C];         // W_proj^T lo
__device__ __nv_bfloat16 g_qvh[Bsz * T * C3];  // qkv hi bf16
__device__ __nv_bfloat16 g_qvl[Bsz * T * C3];  // qkv lo bf16

// ===========================================================================
// PTX helpers (sm_80+ features only: mma.sync / ldmatrix / cp.async)
// ===========================================================================
__device__ __forceinline__ uint32_t smem_u32(const void* p) {
    uint32_t a;
    asm("{ .reg .u64 t; cvta.to.shared.u64 t, %1; cvt.u32.u64 %0, t; }"
        : "=r"(a) : "l"(p));
    return a;
}
__device__ __forceinline__ void cp_async16(uint32_t dst, const void* src) {
    asm volatile("cp.async.cg.shared.global [%0], [%1], 16;"
                 :: "r"(dst), "l"(src) : "memory");
}
__device__ __forceinline__ void cp_commit() {
    asm volatile("cp.async.commit_group;" ::: "memory");
}
template <int N>
__device__ __forceinline__ void cp_wait() {
    asm volatile("cp.async.wait_group %0;" :: "n"(N) : "memory");
}
__device__ __forceinline__ void ldsm_x4(uint32_t& r0, uint32_t& r1,
                                        uint32_t& r2, uint32_t& r3, uint32_t a) {
    asm volatile("ldmatrix.sync.aligned.m8n8.x4.shared.b16 {%0,%1,%2,%3}, [%4];"
                 : "=r"(r0), "=r"(r1), "=r"(r2), "=r"(r3) : "r"(a));
}
__device__ __forceinline__ void ldsm_x4t(uint32_t& r0, uint32_t& r1,
                                         uint32_t& r2, uint32_t& r3, uint32_t a) {
    asm volatile("ldmatrix.sync.aligned.m8n8.x4.trans.shared.b16 {%0,%1,%2,%3}, [%4];"
                 : "=r"(r0), "=r"(r1), "=r"(r2), "=r"(r3) : "r"(a));
}
__device__ __forceinline__ void mma_bf16(float* c, uint32_t a0, uint32_t a1,
                                         uint32_t a2, uint32_t a3,
                                         uint32_t b0, uint32_t b1) {
    asm volatile(
        "mma.sync.aligned.m16n8k16.row.col.f32.bf16.bf16.f32 "
        "{%0,%1,%2,%3}, {%4,%5,%6,%7}, {%8,%9}, {%0,%1,%2,%3};"
        : "+f"(c[0]), "+f"(c[1]), "+f"(c[2]), "+f"(c[3])
        : "r"(a0), "r"(a1), "r"(a2), "r"(a3), "r"(b0), "r"(b1));
}
__device__ __forceinline__ void split2(float a, float b,
                                       uint32_t& hout, uint32_t& lout) {
    __nv_bfloat162 h = __floats2bfloat162_rn(a, b);
    float2 f = __bfloat1622float2(h);
    __nv_bfloat162 l = __floats2bfloat162_rn(a - f.x, b - f.y);
    hout = *(uint32_t*)&h;
    lout = *(uint32_t*)&l;
}

// ===========================================================================
// fp32 -> bf16 hi/lo split (vectorized by 4)
// ===========================================================================
__global__ __launch_bounds__(256) void split_kernel(
    const float* __restrict__ src, __nv_bfloat16* __restrict__ hi,
    __nv_bfloat16* __restrict__ lo, int n4)
{
    int i = blockIdx.x * 256 + threadIdx.x;
    if (i >= n4) return;
    float4 v = ((const float4*)src)[i];
    uint32_t h0, l0, h1, l1;
    split2(v.x, v.y, h0, l0);
    split2(v.z, v.w, h1, l1);
    ((uint32_t*)hi)[2 * i + 0] = h0;
    ((uint32_t*)hi)[2 * i + 1] = h1;
    ((uint32_t*)lo)[2 * i + 0] = l0;
    ((uint32_t*)lo)[2 * i + 1] = l1;
}

// ===========================================================================
// Transpose + split: W (K x N) -> Wt_hi/lo (N x K) bf16
// ===========================================================================
__global__ __launch_bounds__(256) void tsplit_kernel(
    const float* __restrict__ W, __nv_bfloat16* __restrict__ Th,
    __nv_bfloat16* __restrict__ Tl, int K, int N)
{
    __shared__ float t[32][33];
    int n0 = blockIdx.x * 32, k0 = blockIdx.y * 32;
    int tx = threadIdx.x, ty = threadIdx.y;
#pragma unroll
    for (int i = 0; i < 32; i += 8)
        t[ty + i][tx] = W[(size_t)(k0 + ty + i) * N + n0 + tx];
    __syncthreads();
#pragma unroll
    for (int i = 0; i < 32; i += 8) {
        float v = t[tx][ty + i];
        __nv_bfloat16 h = __float2bfloat16(v);
        __nv_bfloat16 l = __float2bfloat16(v - __bfloat162float(h));
        size_t o = (size_t)(n0 + ty + i) * K + k0 + tx;
        Th[o] = h; Tl[o] = l;
    }
}

// ===========================================================================
// mma.sync bf16x3 GEMM — R7 shape: GK=64, ROWB=144, 2-stage, 1 CTA/SM,
// no register cap. Epilogue: fp32 out (Cf) and/or bf16 hi/lo split (Oh/Ol).
// ===========================================================================
#define GK 64
#define ROWB 144                       // 128B data + 16B pad per row
#define MATB (128 * ROWB)              // 18432
#define STAGEB (4 * MATB)              // 73728
#define GEMM_SMEM_BYTES (2 * STAGEB)   // 147456

__global__ __launch_bounds__(256) void gemm_mma_kernel(
    const __nv_bfloat16* __restrict__ Ah, const __nv_bfloat16* __restrict__ Al,
    const __nv_bfloat16* __restrict__ Bh, const __nv_bfloat16* __restrict__ Bl,
    const float* __restrict__ bias, float* __restrict__ Cf,
    __nv_bfloat16* __restrict__ Oh, __nv_bfloat16* __restrict__ Ol,
    int M, int N, int K)
{
    extern __shared__ char smem[];
    const uint32_t sb = smem_u32(smem);

    const int tid  = threadIdx.x;
    const int wid  = tid >> 5;
    const int lane = tid & 31;
    const int wm   = wid >> 1;
    const int wn   = wid & 1;
    const int brow = blockIdx.y * 128;
    const int bcol = blockIdx.x * 128;

    const __nv_bfloat16* gbase[4] = {
        Ah + (size_t)brow * K, Al + (size_t)brow * K,
        Bh + (size_t)bcol * K, Bl + (size_t)bcol * K };

    auto issue_stage = [&](int c, int stage) {
        const int kbase = c * GK;
        const uint32_t sst = sb + stage * STAGEB;
#pragma unroll
        for (int m = 0; m < 4; m++) {
            const __nv_bfloat16* gb = gbase[m] + kbase;
            const uint32_t ms = sst + m * MATB;
#pragma unroll
            for (int it = 0; it < 4; it++) {
                int idx = it * 256 + tid;
                int row = idx >> 3, ch = idx & 7;
                cp_async16(ms + row * ROWB + ch * 16,
                           gb + (size_t)row * K + ch * 8);
            }
        }
        cp_commit();
    };

    float acc[2][8][4];
#pragma unroll
    for (int i = 0; i < 2; i++)
#pragma unroll
        for (int j = 0; j < 8; j++)
#pragma unroll
            for (int r = 0; r < 4; r++) acc[i][j][r] = 0.0f;

    const int nchunks = K / GK;   // 16
    issue_stage(0, 0);

    const int aRow = (wm * 32) + (lane & 15);
    const int aK   = (lane >> 4) * 16;
    const int bRow = (wn * 64) + (lane & 7) + ((lane >> 4) << 3);
    const int bK   = ((lane >> 3) & 1) * 16;

    for (int c = 0; c < nchunks; c++) {
        if (c + 1 < nchunks) {
            issue_stage(c + 1, (c + 1) & 1);
            cp_wait<1>();
        } else {
            cp_wait<0>();
        }
        __syncthreads();

        const uint32_t sst = sb + (c & 1) * STAGEB;
        const uint32_t ahBase = sst + 0 * MATB;
        const uint32_t alBase = sst + 1 * MATB;
        const uint32_t bhBase = sst + 2 * MATB;
        const uint32_t blBase = sst + 3 * MATB;

#pragma unroll
        for (int ks = 0; ks < 4; ks++) {
            const int ko = ks * 32;
            uint32_t ahf[2][4], alf[2][4];
#pragma unroll
            for (int mt = 0; mt < 2; mt++) {
                uint32_t off = (uint32_t)((aRow + mt * 16) * ROWB + ko + aK);
                ldsm_x4(ahf[mt][0], ahf[mt][1], ahf[mt][2], ahf[mt][3], ahBase + off);
                ldsm_x4(alf[mt][0], alf[mt][1], alf[mt][2], alf[mt][3], alBase + off);
            }
            uint32_t bhf[8][2], blf[8][2];
#pragma unroll
            for (int jp = 0; jp < 4; jp++) {
                uint32_t off = (uint32_t)((bRow + jp * 16) * ROWB + ko + bK);
                ldsm_x4(bhf[2*jp][0], bhf[2*jp][1], bhf[2*jp+1][0], bhf[2*jp+1][1],
                        bhBase + off);
                ldsm_x4(blf[2*jp][0], blf[2*jp][1], blf[2*jp+1][0], blf[2*jp+1][1],
                        blBase + off);
            }
            // product-type outermost: consecutive MMAs hit 16 distinct accs
#pragma unroll
            for (int mt = 0; mt < 2; mt++)
#pragma unroll
                for (int nt = 0; nt < 8; nt++)
                    mma_bf16(acc[mt][nt], ahf[mt][0], ahf[mt][1], ahf[mt][2], ahf[mt][3],
                             bhf[nt][0], bhf[nt][1]);
#pragma unroll
            for (int mt = 0; mt < 2; mt++)
#pragma unroll
                for (int nt = 0; nt < 8; nt++)
                    mma_bf16(acc[mt][nt], ahf[mt][0], ahf[mt][1], ahf[mt][2], ahf[mt][3],
                             blf[nt][0], blf[nt][1]);
#pragma unroll
            for (int mt = 0; mt < 2; mt++)
#pragma unroll
                for (int nt = 0; nt < 8; nt++)
                    mma_bf16(acc[mt][nt], alf[mt][0], alf[mt][1], alf[mt][2], alf[mt][3],
                             bhf[nt][0], bhf[nt][1]);
        }
        __syncthreads();
    }

    const int rbase = brow + wm * 32 + (lane >> 2);
    const int cbase = bcol + wn * 64 + (lane & 3) * 2;
#pragma unroll
    for (int mt = 0; mt < 2; mt++) {
#pragma unroll
        for (int nt = 0; nt < 8; nt++) {
            int row = rbase + mt * 16;
            int col = cbase + nt * 8;
            float2 bb = *(const float2*)(bias + col);
            float v0 = acc[mt][nt][0] + bb.x;
            float v1 = acc[mt][nt][1] + bb.y;
            float v2 = acc[mt][nt][2] + bb.x;
            float v3 = acc[mt][nt][3] + bb.y;
            if (Cf) {
                *(float2*)(Cf + (size_t)row * N + col) = make_float2(v0, v1);
                *(float2*)(Cf + (size_t)(row + 8) * N + col) = make_float2(v2, v3);
            }
            if (Oh) {
                uint32_t h0, l0, h1, l1;
                split2(v0, v1, h0, l0);
                split2(v2, v3, h1, l1);
                *(uint32_t*)(Oh + (size_t)row * N + col) = h0;
                *(uint32_t*)(Ol + (size_t)row * N + col) = l0;
                *(uint32_t*)(Oh + (size_t)(row + 8) * N + col) = h1;
                *(uint32_t*)(Ol + (size_t)(row + 8) * N + col) = l1;
            }
        }
    }
}

// ===========================================================================
// Tensor-core flash attention (64-query CTAs) — unchanged from 471us build
// ===========================================================================
#define FROWB 144
#define FMATB (64 * FROWB)
#define FPADB 4096
#define FSTAGEB (4 * FMATB + FPADB)
#define FQ_BYTES (2 * FMATB)
#define FLASH_SMEM (FQ_BYTES + 2 * FSTAGEB)

__global__ __launch_bounds__(128) void flash_mma_kernel(
    const __nv_bfloat16* __restrict__ qvh, const __nv_bfloat16* __restrict__ qvl,
    const unsigned char* __restrict__ pad,
    __nv_bfloat16* __restrict__ yh, __nv_bfloat16* __restrict__ yl)
{
    extern __shared__ char fsm[];
    const uint32_t sb = smem_u32(fsm);
    const int tid = threadIdx.x, lane = tid & 31, w = tid >> 5;
    const int qt = blockIdx.x;
    const int bh = blockIdx.y;
    const int b = bh >> 4, h = bh & 15;
    const int q0 = qt * 64;

    const uint32_t sQh = sb;
    const uint32_t sQl = sQh + FMATB;
    const uint32_t sStage = sQl + FMATB;

    {
        const size_t rbase = (size_t)(b * T + q0) * C3 + h * HD;
#pragma unroll
        for (int it = 0; it < 4; it++) {
            int idx = it * 128 + tid;
            int row = idx >> 3, ch = idx & 7;
            float4 vh = *(const float4*)(qvh + rbase + (size_t)row * C3 + ch * 8);
            float4 vl = *(const float4*)(qvl + rbase + (size_t)row * C3 + ch * 8);
            *(float4*)(fsm + (sQh - sb) + row * FROWB + ch * 16) = vh;
            *(float4*)(fsm + (sQl - sb) + row * FROWB + ch * 16) = vl;
        }
    }

    auto load_stage = [&](int kt, int stg) {
        const uint32_t ss = sStage + stg * FSTAGEB;
        const int kr0 = kt * 64;
        const __nv_bfloat16* srcs[4] = {
            qvh + C + h * HD, qvl + C + h * HD,
            qvh + 2 * C + h * HD, qvl + 2 * C + h * HD };
#pragma unroll
        for (int m = 0; m < 4; m++) {
            const __nv_bfloat16* s = srcs[m];
            const uint32_t ms = ss + m * FMATB;
#pragma unroll
            for (int it = 0; it < 4; it++) {
                int idx = it * 128 + tid;
                int row = idx >> 3, ch = idx & 7;
                cp_async16(ms + row * FROWB + ch * 16,
                           s + (size_t)(b * T + kr0 + row) * C3 + ch * 8);
            }
        }
        const uint32_t ps = ss + 4 * FMATB;
#pragma unroll
        for (int it = 0; it < 2; it++) {
            int idx = it * 128 + tid;
            int row = idx >> 2, ch = idx & 3;
            cp_async16(ps + row * 64 + ch * 16,
                       pad + (size_t)(b * T + q0 + row) * T + kr0 + ch * 16);
        }
        cp_commit();
    };

    const int nkt = qt + 1;
    load_stage(0, 0);
    __syncthreads();

    uint32_t qhF[4][4], qlF[4][4];
    {
        const uint32_t off0 = (uint32_t)((w * 16 + (lane & 15)) * FROWB + (lane >> 4) * 16);
#pragma unroll
        for (int ks = 0; ks < 4; ks++) {
            ldsm_x4(qhF[ks][0], qhF[ks][1], qhF[ks][2], qhF[ks][3], sQh + off0 + ks * 32);
            ldsm_x4(qlF[ks][0], qlF[ks][1], qlF[ks][2], qlF[ks][3], sQl + off0 + ks * 32);
        }
    }

    float o[8][4];
#pragma unroll
    for (int nt = 0; nt < 8; nt++)
#pragma unroll
        for (int r = 0; r < 4; r++) o[nt][r] = 0.0f;
    float m0 = -1e30f, m1 = -1e30f, l0 = 0.0f, l1 = 0.0f;

    const int r0l = w * 16 + (lane >> 2);
    const int gq0 = q0 + r0l, gq1 = gq0 + 8;

    for (int kt = 0; kt < nkt; kt++) {
        if (kt + 1 < nkt) {
            load_stage(kt + 1, (kt + 1) & 1);
            cp_wait<1>();
        } else {
            cp_wait<0>();
        }
        __syncthreads();

        const uint32_t ss = sStage + (kt & 1) * FSTAGEB;
        const uint32_t sKh = ss, sKl = ss + FMATB;
        const uint32_t sVh = ss + 2 * FMATB, sVl = ss + 3 * FMATB;
        const char* pdp = fsm + (ss - sb) + 4 * FMATB;

        float s[8][4];
#pragma unroll
        for (int nt = 0; nt < 8; nt++)
#pragma unroll
            for (int r = 0; r < 4; r++) s[nt][r] = 0.0f;

        const int bRow = (lane & 7) + ((lane >> 4) << 3);
        const int bK   = ((lane >> 3) & 1) * 16;
#pragma unroll
        for (int ks = 0; ks < 4; ks++) {
            uint32_t kh[8][2], kl[8][2];
#pragma unroll
            for (int jp = 0; jp < 4; jp++) {
                uint32_t off = (uint32_t)((jp * 16 + bRow) * FROWB + bK + ks * 32);
                ldsm_x4(kh[2*jp][0], kh[2*jp][1], kh[2*jp+1][0], kh[2*jp+1][1], sKh + off);
                ldsm_x4(kl[2*jp][0], kl[2*jp][1], kl[2*jp+1][0], kl[2*jp+1][1], sKl + off);
            }
#pragma unroll
            for (int nt = 0; nt < 8; nt++)
                mma_bf16(s[nt], qhF[ks][0], qhF[ks][1], qhF[ks][2], qhF[ks][3],
                         kh[nt][0], kh[nt][1]);
#pragma unroll
            for (int nt = 0; nt < 8; nt++)
                mma_bf16(s[nt], qhF[ks][0], qhF[ks][1], qhF[ks][2], qhF[ks][3],
                         kl[nt][0], kl[nt][1]);
#pragma unroll
            for (int nt = 0; nt < 8; nt++)
                mma_bf16(s[nt], qlF[ks][0], qlF[ks][1], qlF[ks][2], qlF[ks][3],
                         kh[nt][0], kh[nt][1]);
        }

        const bool diag = (kt == qt);
#pragma unroll
        for (int nt = 0; nt < 8; nt++) {
            int cl = nt * 8 + (lane & 3) * 2;
            int gk = kt * 64 + cl;
            unsigned short pd0 = *(const unsigned short*)(pdp + r0l * 64 + cl);
            unsigned short pd1 = *(const unsigned short*)(pdp + (r0l + 8) * 64 + cl);
            s[nt][0] *= 0.125f; s[nt][1] *= 0.125f;
            s[nt][2] *= 0.125f; s[nt][3] *= 0.125f;
            if ((diag && gk > gq0)     || (pd0 & 0x00FF)) s[nt][0] = -1e30f;
            if ((diag && gk + 1 > gq0) || (pd0 & 0xFF00)) s[nt][1] = -1e30f;
            if ((diag && gk > gq1)     || (pd1 & 0x00FF)) s[nt][2] = -1e30f;
            if ((diag && gk + 1 > gq1) || (pd1 & 0xFF00)) s[nt][3] = -1e30f;
        }

        float mx0 = -1e30f, mx1 = -1e30f;
#pragma unroll
        for (int nt = 0; nt < 8; nt++) {
            mx0 = fmaxf(mx0, fmaxf(s[nt][0], s[nt][1]));
            mx1 = fmaxf(mx1, fmaxf(s[nt][2], s[nt][3]));
        }
        mx0 = fmaxf(mx0, __shfl_xor_sync(0xFFFFFFFFu, mx0, 1));
        mx0 = fmaxf(mx0, __shfl_xor_sync(0xFFFFFFFFu, mx0, 2));
        mx1 = fmaxf(mx1, __shfl_xor_sync(0xFFFFFFFFu, mx1, 1));
        mx1 = fmaxf(mx1, __shfl_xor_sync(0xFFFFFFFFu, mx1, 2));

        float mn0 = fmaxf(m0, mx0), mn1 = fmaxf(m1, mx1);
        float al0 = __expf(m0 - mn0), al1 = __expf(m1 - mn1);
        float live0 = (mn0 > -1e29f) ? 1.0f : 0.0f;
        float live1 = (mn1 > -1e29f) ? 1.0f : 0.0f;
        m0 = mn0; m1 = mn1;

        float ps0 = 0.f, ps1 = 0.f;
#pragma unroll
        for (int nt = 0; nt < 8; nt++) {
            s[nt][0] = live0 * __expf(s[nt][0] - mn0);
            s[nt][1] = live0 * __expf(s[nt][1] - mn0);
            s[nt][2] = live1 * __expf(s[nt][2] - mn1);
            s[nt][3] = live1 * __expf(s[nt][3] - mn1);
            ps0 += s[nt][0] + s[nt][1];
            ps1 += s[nt][2] + s[nt][3];
        }
        l0 = l0 * al0 + ps0;   // per-lane partial; quad-reduced at epilogue
        l1 = l1 * al1 + ps1;
#pragma unroll
        for (int nt = 0; nt < 8; nt++) {
            o[nt][0] *= al0; o[nt][1] *= al0;
            o[nt][2] *= al1; o[nt][3] *= al1;
        }

        uint32_t pha[4][4], pla[4][4];
#pragma unroll
        for (int ks = 0; ks < 4; ks++) {
#pragma unroll
            for (int t2 = 0; t2 < 2; t2++) {
                int nt = 2 * ks + t2;
                split2(s[nt][0], s[nt][1], pha[ks][2 * t2 + 0], pla[ks][2 * t2 + 0]);
                split2(s[nt][2], s[nt][3], pha[ks][2 * t2 + 1], pla[ks][2 * t2 + 1]);
            }
        }

#pragma unroll
        for (int ks = 0; ks < 4; ks++) {
            uint32_t vh[8][2], vl[8][2];
#pragma unroll
            for (int nb = 0; nb < 4; nb++) {
                uint32_t off = (uint32_t)((ks * 16 + (lane & 7) + ((lane >> 3) & 1) * 8) * FROWB
                                          + (nb * 16 + (lane >> 4) * 8) * 2);
                ldsm_x4t(vh[2*nb][0], vh[2*nb][1], vh[2*nb+1][0], vh[2*nb+1][1], sVh + off);
                ldsm_x4t(vl[2*nb][0], vl[2*nb][1], vl[2*nb+1][0], vl[2*nb+1][1], sVl + off);
            }
#pragma unroll
            for (int nt = 0; nt < 8; nt++)
                mma_bf16(o[nt], pha[ks][0], pha[ks][1], pha[ks][2], pha[ks][3],
                         vh[nt][0], vh[nt][1]);
#pragma unroll
            for (int nt = 0; nt < 8; nt++)
                mma_bf16(o[nt], pha[ks][0], pha[ks][1], pha[ks][2], pha[ks][3],
                         vl[nt][0], vl[nt][1]);
#pragma unroll
            for (int nt = 0; nt < 8; nt++)
                mma_bf16(o[nt], pla[ks][0], pla[ks][1], pla[ks][2], pla[ks][3],
                         vh[nt][0], vh[nt][1]);
        }
        __syncthreads();
    }

    l0 += __shfl_xor_sync(0xFFFFFFFFu, l0, 1);
    l0 += __shfl_xor_sync(0xFFFFFFFFu, l0, 2);
    l1 += __shfl_xor_sync(0xFFFFFFFFu, l1, 1);
    l1 += __shfl_xor_sync(0xFFFFFFFFu, l1, 2);

    float inv0 = (l0 > 0.f) ? (1.0f / l0) : 0.0f;
    float inv1 = (l1 > 0.f) ? (1.0f / l1) : 0.0f;
    const size_t row0 = (size_t)(b * T + gq0);
    const size_t row1 = (size_t)(b * T + gq1);
    const int cb = h * HD + (lane & 3) * 2;
#pragma unroll
    for (int nt = 0; nt < 8; nt++) {
        uint32_t h0, l0b, h1, l1b;
        split2(o[nt][0] * inv0, o[nt][1] * inv0, h0, l0b);
        split2(o[nt][2] * inv1, o[nt][3] * inv1, h1, l1b);
        *(uint32_t*)(yh + row0 * C + cb + nt * 8) = h0;
        *(uint32_t*)(yl + row0 * C + cb + nt * 8) = l0b;
        *(uint32_t*)(yh + row1 * C + cb + nt * 8) = h1;
        *(uint32_t*)(yl + row1 * C + cb + nt * 8) = l1b;
    }
}

// ---------------------------------------------------------------------------
// Head-0 raw logits from bf16 hi/lo qkv (unchanged)
// ---------------------------------------------------------------------------
__global__ __launch_bounds__(128) void att_scores_kernel(
    const __nv_bfloat16* __restrict__ qvh, const __nv_bfloat16* __restrict__ qvl,
    float* __restrict__ att)
{
    const int b  = blockIdx.z;
    const int qt = blockIdx.x;
    const int kt = blockIdx.y;
    const int kbase = kt * 64;
    if (kbase > qt * 128 + 127) return;

    __shared__ float Ks[64 * 64];
    const int tid = threadIdx.x;
#pragma unroll
    for (int i = 0; i < 4; i++) {
        int slot = tid + i * 128;
        int r = slot >> 3;
        int d8 = (slot & 7) * 8;
        const size_t go = (size_t)(b * T + kbase + r) * C3 + C + d8;
        uint4 uh = *(const uint4*)(qvh + go);
        uint4 ul = *(const uint4*)(qvl + go);
        const __nv_bfloat162* ph = (const __nv_bfloat162*)&uh;
        const __nv_bfloat162* pl = (const __nv_bfloat162*)&ul;
        float* dst = Ks + r * 64 + d8;
#pragma unroll
        for (int j = 0; j < 4; j++) {
            float2 fh = __bfloat1622float2(ph[j]);
            float2 fl = __bfloat1622float2(pl[j]);
            dst[2 * j + 0] = fh.x + fl.x;
            dst[2 * j + 1] = fh.y + fl.y;
        }
    }
    const int qi = qt * 128 + tid;
    const size_t qo = (size_t)(b * T + qi) * C3;
    float q[64];
#pragma unroll
    for (int i = 0; i < 8; i++) {
        uint4 uh = *(const uint4*)(qvh + qo + i * 8);
        uint4 ul = *(const uint4*)(qvl + qo + i * 8);
        const __nv_bfloat162* ph = (const __nv_bfloat162*)&uh;
        const __nv_bfloat162* pl = (const __nv_bfloat162*)&ul;
#pragma unroll
        for (int j = 0; j < 4; j++) {
            float2 fh = __bfloat1622float2(ph[j]);
            float2 fl = __bfloat1622float2(pl[j]);
            q[i * 8 + 2 * j + 0] = fh.x + fl.x;
            q[i * 8 + 2 * j + 1] = fh.y + fl.y;
        }
    }
    __syncthreads();

    float* op = att + (size_t)(b * T + qi) * T + kbase;
#pragma unroll
    for (int j0 = 0; j0 < 64; j0 += 4) {
        float sv[4];
#pragma unroll
        for (int jj = 0; jj < 4; jj++) {
            int j = j0 + jj;
            float a0 = 0.f, a1 = 0.f, a2 = 0.f, a3 = 0.f;
#pragma unroll
            for (int d4 = 0; d4 < 16; d4 += 4) {
                float4 k0 = *(const float4*)(Ks + j * 64 + (d4 + 0) * 4);
                float4 k1 = *(const float4*)(Ks + j * 64 + (d4 + 1) * 4);
                float4 k2 = *(const float4*)(Ks + j * 64 + (d4 + 2) * 4);
                float4 k3 = *(const float4*)(Ks + j * 64 + (d4 + 3) * 4);
                a0 += q[(d4+0)*4+0]*k0.x + q[(d4+0)*4+1]*k0.y + q[(d4+0)*4+2]*k0.z + q[(d4+0)*4+3]*k0.w;
                a1 += q[(d4+1)*4+0]*k1.x + q[(d4+1)*4+1]*k1.y + q[(d4+1)*4+2]*k1.z + q[(d4+1)*4+3]*k1.w;
                a2 += q[(d4+2)*4+0]*k2.x + q[(d4+2)*4+1]*k2.y + q[(d4+2)*4+2]*k2.z + q[(d4+2)*4+3]*k2.w;
                a3 += q[(d4+3)*4+0]*k3.x + q[(d4+3)*4+1]*k3.y + q[(d4+3)*4+2]*k3.z + q[(d4+3)*4+3]*k3.w;
            }
            sv[jj] = (a0 + a1 + a2 + a3) * 0.125f;
        }
        float4 r = make_float4(sv[0], sv[1], sv[2], sv[3]);
        *(float4*)(op + j0) = r;
    }
}

// ---------------------------------------------------------------------------
// In-place masked row softmax over att (unchanged)
// ---------------------------------------------------------------------------
__global__ __launch_bounds__(256) void att_softmax_kernel(
    float* __restrict__ att, const unsigned char* __restrict__ pad)
{
    const int row = blockIdx.x;
    const int qi = row & (T - 1);
    float* rp = att + (size_t)row * T;
    const unsigned char* pm = pad + (size_t)row * T;
    const int t = threadIdx.x;

    float x[4];
    float lmax = -1e30f;
#pragma unroll
    for (int i = 0; i < 4; i++) {
        int kj = t + i * 256;
        float v = rp[kj];
        bool m = (kj > qi) || pm[kj];
        x[i] = m ? -1e30f : v;
        lmax = fmaxf(lmax, x[i]);
    }
#pragma unroll
    for (int off = 16; off; off >>= 1)
        lmax = fmaxf(lmax, __shfl_xor_sync(0xFFFFFFFFu, lmax, off));

    __shared__ float sred[8];
    __shared__ float sM, sS;
    const int wid = t >> 5, lane = t & 31;
    if (lane == 0) sred[wid] = lmax;
    __syncthreads();
    if (t == 0) {
        float m = sred[0];
#pragma unroll
        for (int i = 1; i < 8; i++) m = fmaxf(m, sred[i]);
        sM = m;
    }
    __syncthreads();
    const float M = sM;

    float ls = 0.f;
#pragma unroll
    for (int i = 0; i < 4; i++) {
        x[i] = __expf(x[i] - M);
        ls += x[i];
    }
#pragma unroll
    for (int off = 16; off; off >>= 1)
        ls += __shfl_xor_sync(0xFFFFFFFFu, ls, off);
    if (lane == 0) sred[wid] = ls;
    __syncthreads();
    if (t == 0) {
        float s = 0.f;
#pragma unroll
        for (int i = 0; i < 8; i++) s += sred[i];
        sS = s;
    }
    __syncthreads();
    const float inv = (sS > 0.f) ? (1.0f / sS) : 0.0f;
#pragma unroll
    for (int i = 0; i < 4; i++) rp[t + i * 256] = x[i] * inv;
}

// ---------------------------------------------------------------------------
extern "C" void kernel_launch(void* const* d_in, const int* in_sizes, int n_in,
                              void* d_out, int out_size)
{
    const float* x      = (const float*)d_in[0];
    const float* W_attn = (const float*)d_in[1];
    const float* b_attn = (const float*)d_in[2];
    const float* W_proj = (const float*)d_in[3];
    const float* b_proj = (const float*)d_in[4];
    const unsigned char* pad = (const unsigned char*)d_in[5];

    float* y_out   = (float*)d_out;                      // (B,T,C)
    float* att_out = y_out + (size_t)Bsz * T * C;        // (B,1,T,T)

    __nv_bfloat16 *ah = nullptr, *al = nullptr, *wth = nullptr, *wtl = nullptr;
    __nv_bfloat16 *wph = nullptr, *wpl = nullptr;
    __nv_bfloat16 *qvh = nullptr, *qvl = nullptr;
    cudaGetSymbolAddress((void**)&ah, g_ah);
    cudaGetSymbolAddress((void**)&al, g_al);
    cudaGetSymbolAddress((void**)&wth, g_wth);
    cudaGetSymbolAddress((void**)&wtl, g_wtl);
    cudaGetSymbolAddress((void**)&wph, g_wph);
    cudaGetSymbolAddress((void**)&wpl, g_wpl);
    cudaGetSymbolAddress((void**)&qvh, g_qvh);
    cudaGetSymbolAddress((void**)&qvl, g_qvl);

    cudaFuncSetAttribute(gemm_mma_kernel,
                         cudaFuncAttributeMaxDynamicSharedMemorySize,
                         GEMM_SMEM_BYTES);
    cudaFuncSetAttribute(flash_mma_kernel,
                         cudaFuncAttributeMaxDynamicSharedMemorySize,
                         FLASH_SMEM);

    static cudaStream_t s_side = nullptr;
    static cudaEvent_t e_qkv = nullptr, e_att = nullptr, e_wp = nullptr,
                       e_fork = nullptr;
    if (!s_side) {
        cudaStreamCreateWithFlags(&s_side, cudaStreamNonBlocking);
        cudaEventCreateWithFlags(&e_qkv, cudaEventDisableTiming);
        cudaEventCreateWithFlags(&e_att, cudaEventDisableTiming);
        cudaEventCreateWithFlags(&e_wp, cudaEventDisableTiming);
        cudaEventCreateWithFlags(&e_fork, cudaEventDisableTiming);
    }

    const int Mrows = Bsz * T;  // 4096

    cudaEventRecord(e_fork, 0);
    cudaStreamWaitEvent(s_side, e_fork, 0);

    // side: transpose+split W_proj
    tsplit_kernel<<<dim3(C / 32, C / 32), dim3(32, 8), 0, s_side>>>(
        W_proj, wph, wpl, C, C);
    cudaEventRecord(e_wp, s_side);

    // main: split x; transpose+split W_attn
    split_kernel<<<(Mrows * C / 4 + 255) / 256, 256>>>(x, ah, al, Mrows * C / 4);
    tsplit_kernel<<<dim3(C3 / 32, C / 32), dim3(32, 8)>>>(W_attn, wth, wtl, C, C3);

    // main: qkv GEMM (bf16 hi/lo epilogue)
    gemm_mma_kernel<<<dim3(C3 / 128, Mrows / 128), 256, GEMM_SMEM_BYTES>>>(
        ah, al, wth, wtl, b_attn, nullptr, qvh, qvl, Mrows, C3, C);
    cudaEventRecord(e_qkv, 0);

    // side: head-0 att probabilities (concurrent with flash)
    cudaStreamWaitEvent(s_side, e_qkv, 0);
    att_scores_kernel<<<dim3(T / 128, T / 64, Bsz), 128, 0, s_side>>>(
        qvh, qvl, att_out);
    att_softmax_kernel<<<Bsz * T, 256, 0, s_side>>>(att_out, pad);
    cudaEventRecord(e_att, s_side);

    // main: flash attention -> y as bf16 hi/lo
    flash_mma_kernel<<<dim3(T / 64, Bsz * H), 128, FLASH_SMEM>>>(
        qvh, qvl, pad, ah, al);

    // main: proj GEMM
    cudaStreamWaitEvent(0, e_wp, 0);
    gemm_mma_kernel<<<dim3(C / 128, Mrows / 128), 256, GEMM_SMEM_BYTES>>>(
        ah, al, wph, wpl, b_proj, y_out, nullptr, nullptr, Mrows, C, C);

    cudaStreamWaitEvent(0, e_att, 0);
}

// round 17
// speedup vs baseline: 1.4805x; 1.4740x over previous
#include <cuda_runtime.h>
#include <cuda_bf16.h>
#include <cuda_fp16.h>
#include <cstdint>

// Problem constants
#define Bsz 4
#define T 1024
#define C 1024
#define H 16
#define HD 64
#define C3 3072

// Scratch (device globals: allocation-free rule)
__device__ __half g_ah[Bsz * T * C];    // A hi (x-split, then y-split)
__device__ __half g_al[Bsz * T * C];    // A lo
__device__ __half g_wth[C3 * C];        // W_attn^T hi (single-rounded)
__device__ __half g_wph[C * C];         // W_proj^T hi
__device__ __half g_qvh[Bsz * T * C3];  // qkv hi fp16
__device__ __half g_qvl[Bsz * T * C3];  // qkv lo fp16

// ===========================================================================
// PTX helpers (sm_80+ features only: mma.sync / ldmatrix / cp.async)
// ===========================================================================
__device__ __forceinline__ uint32_t smem_u32(const void* p) {
    uint32_t a;
    asm("{ .reg .u64 t; cvta.to.shared.u64 t, %1; cvt.u32.u64 %0, t; }"
        : "=r"(a) : "l"(p));
    return a;
}
__device__ __forceinline__ void cp_async16(uint32_t dst, const void* src) {
    asm volatile("cp.async.cg.shared.global [%0], [%1], 16;"
                 :: "r"(dst), "l"(src) : "memory");
}
__device__ __forceinline__ void cp_commit() {
    asm volatile("cp.async.commit_group;" ::: "memory");
}
template <int N>
__device__ __forceinline__ void cp_wait() {
    asm volatile("cp.async.wait_group %0;" :: "n"(N) : "memory");
}
__device__ __forceinline__ void ldsm_x4(uint32_t& r0, uint32_t& r1,
                                        uint32_t& r2, uint32_t& r3, uint32_t a) {
    asm volatile("ldmatrix.sync.aligned.m8n8.x4.shared.b16 {%0,%1,%2,%3}, [%4];"
                 : "=r"(r0), "=r"(r1), "=r"(r2), "=r"(r3) : "r"(a));
}
__device__ __forceinline__ void ldsm_x4t(uint32_t& r0, uint32_t& r1,
                                         uint32_t& r2, uint32_t& r3, uint32_t a) {
    asm volatile("ldmatrix.sync.aligned.m8n8.x4.trans.shared.b16 {%0,%1,%2,%3}, [%4];"
                 : "=r"(r0), "=r"(r1), "=r"(r2), "=r"(r3) : "r"(a));
}
__device__ __forceinline__ void mma_f16(float* c, uint32_t a0, uint32_t a1,
                                        uint32_t a2, uint32_t a3,
                                        uint32_t b0, uint32_t b1) {
    asm volatile(
        "mma.sync.aligned.m16n8k16.row.col.f32.f16.f16.f32 "
        "{%0,%1,%2,%3}, {%4,%5,%6,%7}, {%8,%9}, {%0,%1,%2,%3};"
        : "+f"(c[0]), "+f"(c[1]), "+f"(c[2]), "+f"(c[3])
        : "r"(a0), "r"(a1), "r"(a2), "r"(a3), "r"(b0), "r"(b1));
}
// fp32 pair -> fp16 hi + fp16 residual lo (packed)
__device__ __forceinline__ void split2h(float a, float b,
                                        uint32_t& hout, uint32_t& lout) {
    __half2 h = __floats2half2_rn(a, b);
    float2 f = __half22float2(h);
    __half2 l = __floats2half2_rn(a - f.x, b - f.y);
    hout = *(uint32_t*)&h;
    lout = *(uint32_t*)&l;
}

// ===========================================================================
// fp32 -> fp16 hi/lo split (vectorized by 4)
// ===========================================================================
__global__ __launch_bounds__(256) void split_kernel(
    const float* __restrict__ src, __half* __restrict__ hi,
    __half* __restrict__ lo, int n4)
{
    int i = blockIdx.x * 256 + threadIdx.x;
    if (i >= n4) return;
    float4 v = ((const float4*)src)[i];
    uint32_t h0, l0, h1, l1;
    split2h(v.x, v.y, h0, l0);
    split2h(v.z, v.w, h1, l1);
    ((uint32_t*)hi)[2 * i + 0] = h0;
    ((uint32_t*)hi)[2 * i + 1] = h1;
    ((uint32_t*)lo)[2 * i + 0] = l0;
    ((uint32_t*)lo)[2 * i + 1] = l1;
}

// ===========================================================================
// Transpose + round: W (K x N) -> Wt_hi (N x K) fp16 (single rounding)
// ===========================================================================
__global__ __launch_bounds__(256) void tsplit_kernel(
    const float* __restrict__ W, __half* __restrict__ Th, int K, int N)
{
    __shared__ float t[32][33];
    int n0 = blockIdx.x * 32, k0 = blockIdx.y * 32;
    int tx = threadIdx.x, ty = threadIdx.y;
#pragma unroll
    for (int i = 0; i < 32; i += 8)
        t[ty + i][tx] = W[(size_t)(k0 + ty + i) * N + n0 + tx];
    __syncthreads();
#pragma unroll
    for (int i = 0; i < 32; i += 8) {
        float v = t[tx][ty + i];
        Th[(size_t)(n0 + ty + i) * K + k0 + tx] = __float2half_rn(v);
    }
}

// ===========================================================================
// mma.sync fp16x2 GEMM: C = (Ah+Al) @ Bh^T + bias.
// GK=64, ROWB=144, 3 matrices per stage (Ah,Al,Bh), 2-stage ring.
// Epilogue: fp32 out (Cf) and/or fp16 hi/lo split (Oh/Ol).
// ===========================================================================
#define GK 64
#define ROWB 144                       // 128B data + 16B pad per row
#define MATB (128 * ROWB)              // 18432
#define STAGEB (3 * MATB)              // 55296
#define GEMM_SMEM_BYTES (2 * STAGEB)   // 110592

__global__ __launch_bounds__(256) void gemm_mma_kernel(
    const __half* __restrict__ Ah, const __half* __restrict__ Al,
    const __half* __restrict__ Bh,
    const float* __restrict__ bias, float* __restrict__ Cf,
    __half* __restrict__ Oh, __half* __restrict__ Ol,
    int M, int N, int K)
{
    extern __shared__ char smem[];
    const uint32_t sb = smem_u32(smem);

    const int tid  = threadIdx.x;
    const int wid  = tid >> 5;
    const int lane = tid & 31;
    const int wm   = wid >> 1;
    const int wn   = wid & 1;
    const int brow = blockIdx.y * 128;
    const int bcol = blockIdx.x * 128;

    const __half* gbase[3] = {
        Ah + (size_t)brow * K, Al + (size_t)brow * K,
        Bh + (size_t)bcol * K };

    auto issue_stage = [&](int c, int stage) {
        const int kbase = c * GK;
        const uint32_t sst = sb + stage * STAGEB;
#pragma unroll
        for (int m = 0; m < 3; m++) {
            const __half* gb = gbase[m] + kbase;
            const uint32_t ms = sst + m * MATB;
#pragma unroll
            for (int it = 0; it < 4; it++) {
                int idx = it * 256 + tid;
                int row = idx >> 3, ch = idx & 7;
                cp_async16(ms + row * ROWB + ch * 16,
                           gb + (size_t)row * K + ch * 8);
            }
        }
        cp_commit();
    };

    float acc[2][8][4];
#pragma unroll
    for (int i = 0; i < 2; i++)
#pragma unroll
        for (int j = 0; j < 8; j++)
#pragma unroll
            for (int r = 0; r < 4; r++) acc[i][j][r] = 0.0f;

    const int nchunks = K / GK;   // 16
    issue_stage(0, 0);

    const int aRow = (wm * 32) + (lane & 15);
    const int aK   = (lane >> 4) * 16;
    const int bRow = (wn * 64) + (lane & 7) + ((lane >> 4) << 3);
    const int bK   = ((lane >> 3) & 1) * 16;

    for (int c = 0; c < nchunks; c++) {
        if (c + 1 < nchunks) {
            issue_stage(c + 1, (c + 1) & 1);
            cp_wait<1>();
        } else {
            cp_wait<0>();
        }
        __syncthreads();

        const uint32_t sst = sb + (c & 1) * STAGEB;
        const uint32_t ahBase = sst + 0 * MATB;
        const uint32_t alBase = sst + 1 * MATB;
        const uint32_t bhBase = sst + 2 * MATB;

#pragma unroll
        for (int ks = 0; ks < 4; ks++) {
            const int ko = ks * 32;
            uint32_t ahf[2][4], alf[2][4];
#pragma unroll
            for (int mt = 0; mt < 2; mt++) {
                uint32_t off = (uint32_t)((aRow + mt * 16) * ROWB + ko + aK);
                ldsm_x4(ahf[mt][0], ahf[mt][1], ahf[mt][2], ahf[mt][3], ahBase + off);
                ldsm_x4(alf[mt][0], alf[mt][1], alf[mt][2], alf[mt][3], alBase + off);
            }
            uint32_t bhf[8][2];
#pragma unroll
            for (int jp = 0; jp < 4; jp++) {
                uint32_t off = (uint32_t)((bRow + jp * 16) * ROWB + ko + bK);
                ldsm_x4(bhf[2*jp][0], bhf[2*jp][1], bhf[2*jp+1][0], bhf[2*jp+1][1],
                        bhBase + off);
            }
            // 2 product rounds; consecutive MMAs hit 16 distinct accumulators
#pragma unroll
            for (int mt = 0; mt < 2; mt++)
#pragma unroll
                for (int nt = 0; nt < 8; nt++)
                    mma_f16(acc[mt][nt], ahf[mt][0], ahf[mt][1], ahf[mt][2], ahf[mt][3],
                            bhf[nt][0], bhf[nt][1]);
#pragma unroll
            for (int mt = 0; mt < 2; mt++)
#pragma unroll
                for (int nt = 0; nt < 8; nt++)
                    mma_f16(acc[mt][nt], alf[mt][0], alf[mt][1], alf[mt][2], alf[mt][3],
                            bhf[nt][0], bhf[nt][1]);
        }
        __syncthreads();
    }

    const int rbase = brow + wm * 32 + (lane >> 2);
    const int cbase = bcol + wn * 64 + (lane & 3) * 2;
#pragma unroll
    for (int mt = 0; mt < 2; mt++) {
#pragma unroll
        for (int nt = 0; nt < 8; nt++) {
            int row = rbase + mt * 16;
            int col = cbase + nt * 8;
            float2 bb = *(const float2*)(bias + col);
            float v0 = acc[mt][nt][0] + bb.x;
            float v1 = acc[mt][nt][1] + bb.y;
            float v2 = acc[mt][nt][2] + bb.x;
            float v3 = acc[mt][nt][3] + bb.y;
            if (Cf) {
                *(float2*)(Cf + (size_t)row * N + col) = make_float2(v0, v1);
                *(float2*)(Cf + (size_t)(row + 8) * N + col) = make_float2(v2, v3);
            }
            if (Oh) {
                uint32_t h0, l0, h1, l1;
                split2h(v0, v1, h0, l0);
                split2h(v2, v3, h1, l1);
                *(uint32_t*)(Oh + (size_t)row * N + col) = h0;
                *(uint32_t*)(Ol + (size_t)row * N + col) = l0;
                *(uint32_t*)(Oh + (size_t)(row + 8) * N + col) = h1;
                *(uint32_t*)(Ol + (size_t)(row + 8) * N + col) = l1;
            }
        }
    }
}

// ===========================================================================
// fp16x2 flash attention: QK^T = (Qh+Ql)·Kh, PV = (Ph+Pl)·Vh.
// 64-query CTAs; stages hold Kh, Vh, pad only (62 KB smem -> 3 CTAs/SM).
// ===========================================================================
#define FROWB 144
#define FMATB (64 * FROWB)             // 9216
#define FPADB 4096
#define FSTAGEB (2 * FMATB + FPADB)    // 22528
#define FQ_BYTES (2 * FMATB)           // Qh + Ql
#define FLASH_SMEM (FQ_BYTES + 2 * FSTAGEB)   // 63488

__global__ __launch_bounds__(128) void flash_mma_kernel(
    const __half* __restrict__ qvh, const __half* __restrict__ qvl,
    const unsigned char* __restrict__ pad,
    __half* __restrict__ yh, __half* __restrict__ yl)
{
    extern __shared__ char fsm[];
    const uint32_t sb = smem_u32(fsm);
    const int tid = threadIdx.x, lane = tid & 31, w = tid >> 5;
    const int qt = blockIdx.x;
    const int bh = blockIdx.y;
    const int b = bh >> 4, h = bh & 15;
    const int q0 = qt * 64;

    const uint32_t sQh = sb;
    const uint32_t sQl = sQh + FMATB;
    const uint32_t sStage = sQl + FMATB;

    {
        const size_t rbase = (size_t)(b * T + q0) * C3 + h * HD;
#pragma unroll
        for (int it = 0; it < 4; it++) {
            int idx = it * 128 + tid;
            int row = idx >> 3, ch = idx & 7;
            float4 vh = *(const float4*)(qvh + rbase + (size_t)row * C3 + ch * 8);
            float4 vl = *(const float4*)(qvl + rbase + (size_t)row * C3 + ch * 8);
            *(float4*)(fsm + (sQh - sb) + row * FROWB + ch * 16) = vh;
            *(float4*)(fsm + (sQl - sb) + row * FROWB + ch * 16) = vl;
        }
    }

    auto load_stage = [&](int kt, int stg) {
        const uint32_t ss = sStage + stg * FSTAGEB;
        const int kr0 = kt * 64;
        const __half* srcs[2] = { qvh + C + h * HD, qvh + 2 * C + h * HD };
#pragma unroll
        for (int m = 0; m < 2; m++) {
            const __half* s = srcs[m];
            const uint32_t ms = ss + m * FMATB;
#pragma unroll
            for (int it = 0; it < 4; it++) {
                int idx = it * 128 + tid;
                int row = idx >> 3, ch = idx & 7;
                cp_async16(ms + row * FROWB + ch * 16,
                           s + (size_t)(b * T + kr0 + row) * C3 + ch * 8);
            }
        }
        const uint32_t ps = ss + 2 * FMATB;
#pragma unroll
        for (int it = 0; it < 2; it++) {
            int idx = it * 128 + tid;
            int row = idx >> 2, ch = idx & 3;
            cp_async16(ps + row * 64 + ch * 16,
                       pad + (size_t)(b * T + q0 + row) * T + kr0 + ch * 16);
        }
        cp_commit();
    };

    const int nkt = qt + 1;
    load_stage(0, 0);
    __syncthreads();

    uint32_t qhF[4][4], qlF[4][4];
    {
        const uint32_t off0 = (uint32_t)((w * 16 + (lane & 15)) * FROWB + (lane >> 4) * 16);
#pragma unroll
        for (int ks = 0; ks < 4; ks++) {
            ldsm_x4(qhF[ks][0], qhF[ks][1], qhF[ks][2], qhF[ks][3], sQh + off0 + ks * 32);
            ldsm_x4(qlF[ks][0], qlF[ks][1], qlF[ks][2], qlF[ks][3], sQl + off0 + ks * 32);
        }
    }

    float o[8][4];
#pragma unroll
    for (int nt = 0; nt < 8; nt++)
#pragma unroll
        for (int r = 0; r < 4; r++) o[nt][r] = 0.0f;
    float m0 = -1e30f, m1 = -1e30f, l0 = 0.0f, l1 = 0.0f;

    const int r0l = w * 16 + (lane >> 2);
    const int gq0 = q0 + r0l, gq1 = gq0 + 8;

    for (int kt = 0; kt < nkt; kt++) {
        if (kt + 1 < nkt) {
            load_stage(kt + 1, (kt + 1) & 1);
            cp_wait<1>();
        } else {
            cp_wait<0>();
        }
        __syncthreads();

        const uint32_t ss = sStage + (kt & 1) * FSTAGEB;
        const uint32_t sKh = ss;
        const uint32_t sVh = ss + FMATB;
        const char* pdp = fsm + (ss - sb) + 2 * FMATB;

        float s[8][4];
#pragma unroll
        for (int nt = 0; nt < 8; nt++)
#pragma unroll
            for (int r = 0; r < 4; r++) s[nt][r] = 0.0f;

        const int bRow = (lane & 7) + ((lane >> 4) << 3);
        const int bK   = ((lane >> 3) & 1) * 16;
#pragma unroll
        for (int ks = 0; ks < 4; ks++) {
            uint32_t kh[8][2];
#pragma unroll
            for (int jp = 0; jp < 4; jp++) {
                uint32_t off = (uint32_t)((jp * 16 + bRow) * FROWB + bK + ks * 32);
                ldsm_x4(kh[2*jp][0], kh[2*jp][1], kh[2*jp+1][0], kh[2*jp+1][1], sKh + off);
            }
#pragma unroll
            for (int nt = 0; nt < 8; nt++)
                mma_f16(s[nt], qhF[ks][0], qhF[ks][1], qhF[ks][2], qhF[ks][3],
                        kh[nt][0], kh[nt][1]);
#pragma unroll
            for (int nt = 0; nt < 8; nt++)
                mma_f16(s[nt], qlF[ks][0], qlF[ks][1], qlF[ks][2], qlF[ks][3],
                        kh[nt][0], kh[nt][1]);
        }

        const bool diag = (kt == qt);
#pragma unroll
        for (int nt = 0; nt < 8; nt++) {
            int cl = nt * 8 + (lane & 3) * 2;
            int gk = kt * 64 + cl;
            unsigned short pd0 = *(const unsigned short*)(pdp + r0l * 64 + cl);
            unsigned short pd1 = *(const unsigned short*)(pdp + (r0l + 8) * 64 + cl);
            s[nt][0] *= 0.125f; s[nt][1] *= 0.125f;
            s[nt][2] *= 0.125f; s[nt][3] *= 0.125f;
            if ((diag && gk > gq0)     || (pd0 & 0x00FF)) s[nt][0] = -1e30f;
            if ((diag && gk + 1 > gq0) || (pd0 & 0xFF00)) s[nt][1] = -1e30f;
            if ((diag && gk > gq1)     || (pd1 & 0x00FF)) s[nt][2] = -1e30f;
            if ((diag && gk + 1 > gq1) || (pd1 & 0xFF00)) s[nt][3] = -1e30f;
        }

        float mx0 = -1e30f, mx1 = -1e30f;
#pragma unroll
        for (int nt = 0; nt < 8; nt++) {
            mx0 = fmaxf(mx0, fmaxf(s[nt][0], s[nt][1]));
            mx1 = fmaxf(mx1, fmaxf(s[nt][2], s[nt][3]));
        }
        mx0 = fmaxf(mx0, __shfl_xor_sync(0xFFFFFFFFu, mx0, 1));
        mx0 = fmaxf(mx0, __shfl_xor_sync(0xFFFFFFFFu, mx0, 2));
        mx1 = fmaxf(mx1, __shfl_xor_sync(0xFFFFFFFFu, mx1, 1));
        mx1 = fmaxf(mx1, __shfl_xor_sync(0xFFFFFFFFu, mx1, 2));

        float mn0 = fmaxf(m0, mx0), mn1 = fmaxf(m1, mx1);
        float al0 = __expf(m0 - mn0), al1 = __expf(m1 - mn1);
        float live0 = (mn0 > -1e29f) ? 1.0f : 0.0f;
        float live1 = (mn1 > -1e29f) ? 1.0f : 0.0f;
        m0 = mn0; m1 = mn1;

        float ps0 = 0.f, ps1 = 0.f;
#pragma unroll
        for (int nt = 0; nt < 8; nt++) {
            s[nt][0] = live0 * __expf(s[nt][0] - mn0);
            s[nt][1] = live0 * __expf(s[nt][1] - mn0);
            s[nt][2] = live1 * __expf(s[nt][2] - mn1);
            s[nt][3] = live1 * __expf(s[nt][3] - mn1);
            ps0 += s[nt][0] + s[nt][1];
            ps1 += s[nt][2] + s[nt][3];
        }
        l0 = l0 * al0 + ps0;   // per-lane partial; quad-reduced at epilogue
        l1 = l1 * al1 + ps1;
#pragma unroll
        for (int nt = 0; nt < 8; nt++) {
            o[nt][0] *= al0; o[nt][1] *= al0;
            o[nt][2] *= al1; o[nt][3] *= al1;
        }

        uint32_t pha[4][4], pla[4][4];
#pragma unroll
        for (int ks = 0; ks < 4; ks++) {
#pragma unroll
            for (int t2 = 0; t2 < 2; t2++) {
                int nt = 2 * ks + t2;
                split2h(s[nt][0], s[nt][1], pha[ks][2 * t2 + 0], pla[ks][2 * t2 + 0]);
                split2h(s[nt][2], s[nt][3], pha[ks][2 * t2 + 1], pla[ks][2 * t2 + 1]);
            }
        }

#pragma unroll
        for (int ks = 0; ks < 4; ks++) {
            uint32_t vh[8][2];
#pragma unroll
            for (int nb = 0; nb < 4; nb++) {
                uint32_t off = (uint32_t)((ks * 16 + (lane & 7) + ((lane >> 3) & 1) * 8) * FROWB
                                          + (nb * 16 + (lane >> 4) * 8) * 2);
                ldsm_x4t(vh[2*nb][0], vh[2*nb][1], vh[2*nb+1][0], vh[2*nb+1][1], sVh + off);
            }
#pragma unroll
            for (int nt = 0; nt < 8; nt++)
                mma_f16(o[nt], pha[ks][0], pha[ks][1], pha[ks][2], pha[ks][3],
                        vh[nt][0], vh[nt][1]);
#pragma unroll
            for (int nt = 0; nt < 8; nt++)
                mma_f16(o[nt], pla[ks][0], pla[ks][1], pla[ks][2], pla[ks][3],
                        vh[nt][0], vh[nt][1]);
        }
        __syncthreads();
    }

    l0 += __shfl_xor_sync(0xFFFFFFFFu, l0, 1);
    l0 += __shfl_xor_sync(0xFFFFFFFFu, l0, 2);
    l1 += __shfl_xor_sync(0xFFFFFFFFu, l1, 1);
    l1 += __shfl_xor_sync(0xFFFFFFFFu, l1, 2);

    float inv0 = (l0 > 0.f) ? (1.0f / l0) : 0.0f;
    float inv1 = (l1 > 0.f) ? (1.0f / l1) : 0.0f;
    const size_t row0 = (size_t)(b * T + gq0);
    const size_t row1 = (size_t)(b * T + gq1);
    const int cb = h * HD + (lane & 3) * 2;
#pragma unroll
    for (int nt = 0; nt < 8; nt++) {
        uint32_t h0, l0b, h1, l1b;
        split2h(o[nt][0] * inv0, o[nt][1] * inv0, h0, l0b);
        split2h(o[nt][2] * inv1, o[nt][3] * inv1, h1, l1b);
        *(uint32_t*)(yh + row0 * C + cb + nt * 8) = h0;
        *(uint32_t*)(yl + row0 * C + cb + nt * 8) = l0b;
        *(uint32_t*)(yh + row1 * C + cb + nt * 8) = h1;
        *(uint32_t*)(yl + row1 * C + cb + nt * 8) = l1b;
    }
}

// ---------------------------------------------------------------------------
// Head-0 raw logits from fp16 hi/lo qkv (fp32 reconstruction = hi + lo)
// ---------------------------------------------------------------------------
__global__ __launch_bounds__(128) void att_scores_kernel(
    const __half* __restrict__ qvh, const __half* __restrict__ qvl,
    float* __restrict__ att)
{
    const int b  = blockIdx.z;
    const int qt = blockIdx.x;
    const int kt = blockIdx.y;
    const int kbase = kt * 64;
    if (kbase > qt * 128 + 127) return;

    __shared__ float Ks[64 * 64];
    const int tid = threadIdx.x;
#pragma unroll
    for (int i = 0; i < 4; i++) {
        int slot = tid + i * 128;
        int r = slot >> 3;
        int d8 = (slot & 7) * 8;
        const size_t go = (size_t)(b * T + kbase + r) * C3 + C + d8;
        uint4 uh = *(const uint4*)(qvh + go);
        uint4 ul = *(const uint4*)(qvl + go);
        const __half2* ph = (const __half2*)&uh;
        const __half2* pl = (const __half2*)&ul;
        float* dst = Ks + r * 64 + d8;
#pragma unroll
        for (int j = 0; j < 4; j++) {
            float2 fh = __half22float2(ph[j]);
            float2 fl = __half22float2(pl[j]);
            dst[2 * j + 0] = fh.x + fl.x;
            dst[2 * j + 1] = fh.y + fl.y;
        }
    }
    const int qi = qt * 128 + tid;
    const size_t qo = (size_t)(b * T + qi) * C3;
    float q[64];
#pragma unroll
    for (int i = 0; i < 8; i++) {
        uint4 uh = *(const uint4*)(qvh + qo + i * 8);
        uint4 ul = *(const uint4*)(qvl + qo + i * 8);
        const __half2* ph = (const __half2*)&uh;
        const __half2* pl = (const __half2*)&ul;
#pragma unroll
        for (int j = 0; j < 4; j++) {
            float2 fh = __half22float2(ph[j]);
            float2 fl = __half22float2(pl[j]);
            q[i * 8 + 2 * j + 0] = fh.x + fl.x;
            q[i * 8 + 2 * j + 1] = fh.y + fl.y;
        }
    }
    __syncthreads();

    float* op = att + (size_t)(b * T + qi) * T + kbase;
#pragma unroll
    for (int j0 = 0; j0 < 64; j0 += 4) {
        float sv[4];
#pragma unroll
        for (int jj = 0; jj < 4; jj++) {
            int j = j0 + jj;
            float a0 = 0.f, a1 = 0.f, a2 = 0.f, a3 = 0.f;
#pragma unroll
            for (int d4 = 0; d4 < 16; d4 += 4) {
                float4 k0 = *(const float4*)(Ks + j * 64 + (d4 + 0) * 4);
                float4 k1 = *(const float4*)(Ks + j * 64 + (d4 + 1) * 4);
                float4 k2 = *(const float4*)(Ks + j * 64 + (d4 + 2) * 4);
                float4 k3 = *(const float4*)(Ks + j * 64 + (d4 + 3) * 4);
                a0 += q[(d4+0)*4+0]*k0.x + q[(d4+0)*4+1]*k0.y + q[(d4+0)*4+2]*k0.z + q[(d4+0)*4+3]*k0.w;
                a1 += q[(d4+1)*4+0]*k1.x + q[(d4+1)*4+1]*k1.y + q[(d4+1)*4+2]*k1.z + q[(d4+1)*4+3]*k1.w;
                a2 += q[(d4+2)*4+0]*k2.x + q[(d4+2)*4+1]*k2.y + q[(d4+2)*4+2]*k2.z + q[(d4+2)*4+3]*k2.w;
                a3 += q[(d4+3)*4+0]*k3.x + q[(d4+3)*4+1]*k3.y + q[(d4+3)*4+2]*k3.z + q[(d4+3)*4+3]*k3.w;
            }
            sv[jj] = (a0 + a1 + a2 + a3) * 0.125f;
        }
        float4 r = make_float4(sv[0], sv[1], sv[2], sv[3]);
        *(float4*)(op + j0) = r;
    }
}

// ---------------------------------------------------------------------------
// In-place masked row softmax over att (unchanged)
// ---------------------------------------------------------------------------
__global__ __launch_bounds__(256) void att_softmax_kernel(
    float* __restrict__ att, const unsigned char* __restrict__ pad)
{
    const int row = blockIdx.x;
    const int qi = row & (T - 1);
    float* rp = att + (size_t)row * T;
    const unsigned char* pm = pad + (size_t)row * T;
    const int t = threadIdx.x;

    float x[4];
    float lmax = -1e30f;
#pragma unroll
    for (int i = 0; i < 4; i++) {
        int kj = t + i * 256;
        float v = rp[kj];
        bool m = (kj > qi) || pm[kj];
        x[i] = m ? -1e30f : v;
        lmax = fmaxf(lmax, x[i]);
    }
#pragma unroll
    for (int off = 16; off; off >>= 1)
        lmax = fmaxf(lmax, __shfl_xor_sync(0xFFFFFFFFu, lmax, off));

    __shared__ float sred[8];
    __shared__ float sM, sS;
    const int wid = t >> 5, lane = t & 31;
    if (lane == 0) sred[wid] = lmax;
    __syncthreads();
    if (t == 0) {
        float m = sred[0];
#pragma unroll
        for (int i = 1; i < 8; i++) m = fmaxf(m, sred[i]);
        sM = m;
    }
    __syncthreads();
    const float M = sM;

    float ls = 0.f;
#pragma unroll
    for (int i = 0; i < 4; i++) {
        x[i] = __expf(x[i] - M);
        ls += x[i];
    }
#pragma unroll
    for (int off = 16; off; off >>= 1)
        ls += __shfl_xor_sync(0xFFFFFFFFu, ls, off);
    if (lane == 0) sred[wid] = ls;
    __syncthreads();
    if (t == 0) {
        float s = 0.f;
#pragma unroll
        for (int i = 0; i < 8; i++) s += sred[i];
        sS = s;
    }
    __syncthreads();
    const float inv = (sS > 0.f) ? (1.0f / sS) : 0.0f;
#pragma unroll
    for (int i = 0; i < 4; i++) rp[t + i * 256] = x[i] * inv;
}

// ---------------------------------------------------------------------------
extern "C" void kernel_launch(void* const* d_in, const int* in_sizes, int n_in,
                              void* d_out, int out_size)
{
    const float* x      = (const float*)d_in[0];
    const float* W_attn = (const float*)d_in[1];
    const float* b_attn = (const float*)d_in[2];
    const float* W_proj = (const float*)d_in[3];
    const float* b_proj = (const float*)d_in[4];
    const unsigned char* pad = (const unsigned char*)d_in[5];

    float* y_out   = (float*)d_out;                      // (B,T,C)
    float* att_out = y_out + (size_t)Bsz * T * C;        // (B,1,T,T)

    __half *ah = nullptr, *al = nullptr, *wth = nullptr, *wph = nullptr;
    __half *qvh = nullptr, *qvl = nullptr;
    cudaGetSymbolAddress((void**)&ah, g_ah);
    cudaGetSymbolAddress((void**)&al, g_al);
    cudaGetSymbolAddress((void**)&wth, g_wth);
    cudaGetSymbolAddress((void**)&wph, g_wph);
    cudaGetSymbolAddress((void**)&qvh, g_qvh);
    cudaGetSymbolAddress((void**)&qvl, g_qvl);

    cudaFuncSetAttribute(gemm_mma_kernel,
                         cudaFuncAttributeMaxDynamicSharedMemorySize,
                         GEMM_SMEM_BYTES);
    cudaFuncSetAttribute(flash_mma_kernel,
                         cudaFuncAttributeMaxDynamicSharedMemorySize,
                         FLASH_SMEM);

    static cudaStream_t s_side = nullptr;
    static cudaEvent_t e_qkv = nullptr, e_att = nullptr, e_wp = nullptr,
                       e_fork = nullptr;
    if (!s_side) {
        cudaStreamCreateWithFlags(&s_side, cudaStreamNonBlocking);
        cudaEventCreateWithFlags(&e_qkv, cudaEventDisableTiming);
        cudaEventCreateWithFlags(&e_att, cudaEventDisableTiming);
        cudaEventCreateWithFlags(&e_wp, cudaEventDisableTiming);
        cudaEventCreateWithFlags(&e_fork, cudaEventDisableTiming);
    }

    const int Mrows = Bsz * T;  // 4096

    cudaEventRecord(e_fork, 0);
    cudaStreamWaitEvent(s_side, e_fork, 0);

    // side: transpose+round W_proj
    tsplit_kernel<<<dim3(C / 32, C / 32), dim3(32, 8), 0, s_side>>>(
        W_proj, wph, C, C);
    cudaEventRecord(e_wp, s_side);

    // main: split x; transpose+round W_attn
    split_kernel<<<(Mrows * C / 4 + 255) / 256, 256>>>(x, ah, al, Mrows * C / 4);
    tsplit_kernel<<<dim3(C3 / 32, C / 32), dim3(32, 8)>>>(W_attn, wth, C, C3);

    // main: qkv GEMM (fp16 hi/lo epilogue)
    gemm_mma_kernel<<<dim3(C3 / 128, Mrows / 128), 256, GEMM_SMEM_BYTES>>>(
        ah, al, wth, b_attn, nullptr, qvh, qvl, Mrows, C3, C);
    cudaEventRecord(e_qkv, 0);

    // side: head-0 att probabilities (concurrent with flash)
    cudaStreamWaitEvent(s_side, e_qkv, 0);
    att_scores_kernel<<<dim3(T / 128, T / 64, Bsz), 128, 0, s_side>>>(
        qvh, qvl, att_out);
    att_softmax_kernel<<<Bsz * T, 256, 0, s_side>>>(att_out, pad);
    cudaEventRecord(e_att, s_side);

    // main: flash attention -> y as fp16 hi/lo
    flash_mma_kernel<<<dim3(T / 64, Bsz * H), 128, FLASH_SMEM>>>(
        qvh, qvl, pad, ah, al);

    // main: proj GEMM
    cudaStreamWaitEvent(0, e_wp, 0);
    gemm_mma_kernel<<<dim3(C / 128, Mrows / 128), 256, GEMM_SMEM_BYTES>>>(
        ah, al, wph, b_proj, y_out, nullptr, nullptr, Mrows, C, C);

    cudaStreamWaitEvent(0, e_att, 0);
}